// round 1
// baseline (speedup 1.0000x reference)
#include <cuda_runtime.h>
#include <cstdint>

// ---------------------------------------------------------------------------
// TSABlock on GB300: fp32 SIMT baseline (Round 1)
//   y    = x @ W_down^T + b_down + broadcast(t @ W_t^T + b_t)
//   qkv  = y @ W_qkv^T + b_qkv
//   attn = per-row 8x8 attention over [8,64] views of each qkv row
//   out  = attn @ W_out^T + b_out
// ---------------------------------------------------------------------------

#define N_ROWS   65536      // BS*CLIP
#define N_BATCH  8192
#define IN_CH    1024
#define OUT_CH   512
#define T_DIM    512
#define QKV_CH   1536

// Scratch (no cudaMalloc allowed -> __device__ globals)
__device__ float g_temb[N_BATCH * OUT_CH];          //  16.8 MB
__device__ float g_y   [N_ROWS * OUT_CH];           // 134.2 MB
__device__ float g_qkv [N_ROWS * QKV_CH];           // 402.7 MB
__device__ float g_att [N_ROWS * OUT_CH];           // 134.2 MB

// ---------------------------------------------------------------------------
// GEMM (NT): C[m,n] = sum_k A[m,k] * B[n,k]  (+ bias[n]) (+ addv[(m>>3),n])
// Tile: 128x128x8, 256 threads, 8x8 per-thread accumulators.
// EPI bit0: add bias.  EPI bit1: add temb broadcast (row m -> batch m>>3).
// ---------------------------------------------------------------------------
template<int EPI>
__global__ __launch_bounds__(256, 2)
void gemm_nt(const float* __restrict__ A, const float* __restrict__ B,
             const float* __restrict__ bias, const float* __restrict__ addv,
             float* __restrict__ C, int M, int N, int K)
{
    __shared__ float As[8][132];
    __shared__ float Bs[8][132];

    const int tid     = threadIdx.x;
    const int loadRow = tid >> 1;          // 0..127
    const int loadK   = (tid & 1) * 4;     // 0 or 4
    const int tx      = tid & 15;          // n-frag
    const int ty      = tid >> 4;          // m-frag

    const float* Aptr = A + (size_t)(blockIdx.y * 128 + loadRow) * K + loadK;
    const float* Bptr = B + (size_t)(blockIdx.x * 128 + loadRow) * K + loadK;

    float acc[8][8];
#pragma unroll
    for (int i = 0; i < 8; i++)
#pragma unroll
        for (int j = 0; j < 8; j++) acc[i][j] = 0.0f;

    for (int k0 = 0; k0 < K; k0 += 8) {
        float4 av = *reinterpret_cast<const float4*>(Aptr + k0);
        float4 bv = *reinterpret_cast<const float4*>(Bptr + k0);
        As[loadK + 0][loadRow] = av.x;
        As[loadK + 1][loadRow] = av.y;
        As[loadK + 2][loadRow] = av.z;
        As[loadK + 3][loadRow] = av.w;
        Bs[loadK + 0][loadRow] = bv.x;
        Bs[loadK + 1][loadRow] = bv.y;
        Bs[loadK + 2][loadRow] = bv.z;
        Bs[loadK + 3][loadRow] = bv.w;
        __syncthreads();

#pragma unroll
        for (int kk = 0; kk < 8; kk++) {
            float a[8], b[8];
            *reinterpret_cast<float4*>(&a[0]) =
                *reinterpret_cast<const float4*>(&As[kk][ty * 8]);
            *reinterpret_cast<float4*>(&a[4]) =
                *reinterpret_cast<const float4*>(&As[kk][ty * 8 + 4]);
            *reinterpret_cast<float4*>(&b[0]) =
                *reinterpret_cast<const float4*>(&Bs[kk][tx * 8]);
            *reinterpret_cast<float4*>(&b[4]) =
                *reinterpret_cast<const float4*>(&Bs[kk][tx * 8 + 4]);
#pragma unroll
            for (int i = 0; i < 8; i++)
#pragma unroll
                for (int j = 0; j < 8; j++)
                    acc[i][j] = fmaf(a[i], b[j], acc[i][j]);
        }
        __syncthreads();
    }

    const int nb = blockIdx.x * 128 + tx * 8;
    float bb[8];
#pragma unroll
    for (int j = 0; j < 8; j++) bb[j] = (EPI & 1) ? bias[nb + j] : 0.0f;

#pragma unroll
    for (int i = 0; i < 8; i++) {
        const int m = blockIdx.y * 128 + ty * 8 + i;
        float v[8];
#pragma unroll
        for (int j = 0; j < 8; j++) v[j] = acc[i][j] + bb[j];
        if (EPI & 2) {
            const float* ap = addv + (size_t)(m >> 3) * N + nb;
#pragma unroll
            for (int j = 0; j < 8; j++) v[j] += ap[j];
        }
        float* cp = C + (size_t)m * N + nb;
        reinterpret_cast<float4*>(cp)[0] = make_float4(v[0], v[1], v[2], v[3]);
        reinterpret_cast<float4*>(cp)[1] = make_float4(v[4], v[5], v[6], v[7]);
    }
}

// ---------------------------------------------------------------------------
// Per-row attention. Each qkv row (1536 floats) = Q,K,V as [8,64] each.
//   W = softmax( (Q K^T) / 8 ),  out_row = W V  (flattened back to 512)
// One warp per row; 8 rows per 256-thread block (48 KB smem staging).
// Lane l: i = l&7 (query idx), cc = l>>3 -> 16-channel chunk [cc*16, cc*16+16).
// ---------------------------------------------------------------------------
__global__ __launch_bounds__(256)
void attn_kernel(const float* __restrict__ qkv, float* __restrict__ out)
{
    __shared__ float s[8 * QKV_CH];   // 48 KB
    const int tid = threadIdx.x;
    const size_t row0 = (size_t)blockIdx.x * 8;

    const float4* src = reinterpret_cast<const float4*>(qkv + row0 * QKV_CH);
    float4* dst = reinterpret_cast<float4*>(s);
#pragma unroll
    for (int i = 0; i < 12; i++) dst[tid + i * 256] = src[tid + i * 256];
    __syncthreads();

    const int warp = tid >> 5;
    const int lane = tid & 31;
    const float* qs = s + warp * QKV_CH;
    const float* ks = qs + 512;
    const float* vs = qs + 1024;
    const int i  = lane & 7;
    const int c0 = (lane >> 3) * 16;

    float qreg[16];
#pragma unroll
    for (int c = 0; c < 16; c++) qreg[c] = qs[i * 64 + c0 + c];

    float w[8];
#pragma unroll
    for (int j = 0; j < 8; j++) {
        float acc = 0.0f;
#pragma unroll
        for (int c = 0; c < 16; c++)
            acc = fmaf(qreg[c], ks[j * 64 + c0 + c], acc);
        acc += __shfl_xor_sync(0xffffffffu, acc, 8);
        acc += __shfl_xor_sync(0xffffffffu, acc, 16);
        w[j] = acc * 0.125f;   // scale^2 = 1/sqrt(64)
    }

    float mx = w[0];
#pragma unroll
    for (int j = 1; j < 8; j++) mx = fmaxf(mx, w[j]);
    float sum = 0.0f;
#pragma unroll
    for (int j = 0; j < 8; j++) { w[j] = __expf(w[j] - mx); sum += w[j]; }
    const float inv = 1.0f / sum;

    float o[16];
#pragma unroll
    for (int c = 0; c < 16; c++) o[c] = 0.0f;
#pragma unroll
    for (int j = 0; j < 8; j++) {
        const float wj = w[j];
#pragma unroll
        for (int c = 0; c < 16; c++)
            o[c] = fmaf(wj, vs[j * 64 + c0 + c], o[c]);
    }

    float* op = out + (row0 + warp) * (size_t)OUT_CH + i * 64 + c0;
#pragma unroll
    for (int q = 0; q < 4; q++)
        reinterpret_cast<float4*>(op)[q] =
            make_float4(o[4 * q + 0] * inv, o[4 * q + 1] * inv,
                        o[4 * q + 2] * inv, o[4 * q + 3] * inv);
}

// ---------------------------------------------------------------------------
extern "C" void kernel_launch(void* const* d_in, const int* in_sizes, int n_in,
                              void* d_out, int out_size)
{
    const float* x      = (const float*)d_in[0];
    const float* t      = (const float*)d_in[1];
    const float* W_down = (const float*)d_in[2];
    const float* b_down = (const float*)d_in[3];
    const float* W_t    = (const float*)d_in[4];
    const float* b_t    = (const float*)d_in[5];
    const float* W_qkv  = (const float*)d_in[6];
    const float* b_qkv  = (const float*)d_in[7];
    const float* W_out  = (const float*)d_in[8];
    const float* b_out  = (const float*)d_in[9];
    float* out = (float*)d_out;

    float *temb, *y, *qkv, *att;
    cudaGetSymbolAddress((void**)&temb, g_temb);
    cudaGetSymbolAddress((void**)&y,    g_y);
    cudaGetSymbolAddress((void**)&qkv,  g_qkv);
    cudaGetSymbolAddress((void**)&att,  g_att);

    const dim3 blk(256);

    // temb = t @ W_t^T + b_t                       [8192, 512]
    gemm_nt<1><<<dim3(T_DIM / 128, N_BATCH / 128), blk>>>(
        t, W_t, b_t, nullptr, temb, N_BATCH, OUT_CH, T_DIM);

    // y = x @ W_down^T + b_down + temb[batch]      [65536, 512]
    gemm_nt<3><<<dim3(OUT_CH / 128, N_ROWS / 128), blk>>>(
        x, W_down, b_down, temb, y, N_ROWS, OUT_CH, IN_CH);

    // qkv = y @ W_qkv^T + b_qkv                    [65536, 1536]
    gemm_nt<1><<<dim3(QKV_CH / 128, N_ROWS / 128), blk>>>(
        y, W_qkv, b_qkv, nullptr, qkv, N_ROWS, QKV_CH, OUT_CH);

    // att = rowwise attention(qkv)                 [65536, 512]
    attn_kernel<<<N_ROWS / 8, 256>>>(qkv, att);

    // out = att @ W_out^T + b_out                  [65536, 512]
    gemm_nt<1><<<dim3(OUT_CH / 128, N_ROWS / 128), blk>>>(
        att, W_out, b_out, nullptr, out, N_ROWS, OUT_CH, OUT_CH);
}

// round 3
// speedup vs baseline: 1.5781x; 1.5781x over previous
#include <cuda_runtime.h>
#include <cuda_bf16.h>
#include <cstdint>

// ---------------------------------------------------------------------------
// TSABlock — mma.sync (bf16 hi/lo 3-term split) GEMMs; compute_103-safe PTX.
//   All GEMMs: C = A @ B^T (+epilogue), A[M,K], B[N,K] K-major.
// ---------------------------------------------------------------------------

#define N_ROWS   65536
#define N_BATCH  8192
#define IN_CH    1024
#define OUT_CH   512
#define T_DIM    512
#define QKV_CH   1536

#define BM 128
#define BN 128
#define BK 32
static constexpr int STAGE_BYTES = (BM + BN) * 128;   // 32 KB (hi+lo packed rows)
static constexpr int NSTAGE = 3;
static constexpr int SMEM_BYTES = NSTAGE * STAGE_BYTES;   // 96 KB

// ------------------------- device scratch (no cudaMalloc) -------------------
__device__ __align__(16) __nv_bfloat16 g_xh [N_ROWS * IN_CH];
__device__ __align__(16) __nv_bfloat16 g_xl [N_ROWS * IN_CH];
__device__ __align__(16) __nv_bfloat16 g_th [N_BATCH * T_DIM];
__device__ __align__(16) __nv_bfloat16 g_tl [N_BATCH * T_DIM];
__device__ __align__(16) __nv_bfloat16 g_Wdh[OUT_CH * IN_CH];
__device__ __align__(16) __nv_bfloat16 g_Wdl[OUT_CH * IN_CH];
__device__ __align__(16) __nv_bfloat16 g_Wth[OUT_CH * T_DIM];
__device__ __align__(16) __nv_bfloat16 g_Wtl[OUT_CH * T_DIM];
__device__ __align__(16) __nv_bfloat16 g_Wqh[QKV_CH * OUT_CH];
__device__ __align__(16) __nv_bfloat16 g_Wql[QKV_CH * OUT_CH];
__device__ __align__(16) __nv_bfloat16 g_Woh[OUT_CH * OUT_CH];
__device__ __align__(16) __nv_bfloat16 g_Wol[OUT_CH * OUT_CH];
__device__ __align__(16) float         g_temb[N_BATCH * OUT_CH];
__device__ __align__(16) __nv_bfloat16 g_yh [N_ROWS * OUT_CH];
__device__ __align__(16) __nv_bfloat16 g_yl [N_ROWS * OUT_CH];
__device__ __align__(16) float         g_qkv[N_ROWS * QKV_CH];
__device__ __align__(16) __nv_bfloat16 g_ath[N_ROWS * OUT_CH];
__device__ __align__(16) __nv_bfloat16 g_atl[N_ROWS * OUT_CH];

// ------------------------------ PTX helpers --------------------------------
__device__ __forceinline__ uint32_t smem_u32(const void* p) {
    uint32_t a;
    asm("{ .reg .u64 t; cvta.to.shared.u64 t, %1; cvt.u32.u64 %0, t; }"
        : "=r"(a) : "l"(p));
    return a;
}
#define CP_COMMIT() asm volatile("cp.async.commit_group;" ::: "memory")
#define CP_WAIT1()  asm volatile("cp.async.wait_group 1;" ::: "memory")

__device__ __forceinline__ void cp16(uint32_t dst, const void* src) {
    asm volatile("cp.async.cg.shared.global [%0], [%1], 16;" :: "r"(dst), "l"(src));
}

__device__ __forceinline__ void ldsm_x4(uint32_t& r0, uint32_t& r1,
                                        uint32_t& r2, uint32_t& r3, uint32_t a) {
    asm volatile("ldmatrix.sync.aligned.m8n8.x4.shared.b16 {%0,%1,%2,%3}, [%4];"
                 : "=r"(r0), "=r"(r1), "=r"(r2), "=r"(r3) : "r"(a));
}

__device__ __forceinline__ void mma16816(float* d, const uint32_t* a, const uint32_t* b) {
    asm volatile(
        "mma.sync.aligned.m16n8k16.row.col.f32.bf16.bf16.f32 "
        "{%0,%1,%2,%3}, {%4,%5,%6,%7}, {%8,%9}, {%0,%1,%2,%3};"
        : "+f"(d[0]), "+f"(d[1]), "+f"(d[2]), "+f"(d[3])
        : "r"(a[0]), "r"(a[1]), "r"(a[2]), "r"(a[3]), "r"(b[0]), "r"(b[1]));
}

// ------------------------------ stage copy ---------------------------------
// Each smem row = 128 B: [hi k0..31 | lo k0..31] bf16, XOR-8 16B-chunk swizzle.
__device__ __forceinline__ void stage_copy(
    const __nv_bfloat16* __restrict__ Ah, const __nv_bfloat16* __restrict__ Al,
    const __nv_bfloat16* __restrict__ Bh, const __nv_bfloat16* __restrict__ Bl,
    int K, int m0, int n0, int k0, uint32_t sbase, int tid)
{
#pragma unroll
    for (int i = 0; i < 8; i++) {
        int id   = tid + i * 256;          // 0..2047
        int part = id >> 9;                // 0 Ahi, 1 Alo, 2 Bhi, 3 Blo
        int rid  = (id >> 2) & 127;
        int c    = id & 3;
        const __nv_bfloat16* src;
        uint32_t base;
        int cc;
        if (part < 2) {
            src  = (part == 0 ? Ah : Al) + (size_t)(m0 + rid) * K + k0 + c * 8;
            cc   = c + (part == 0 ? 0 : 4);
            base = sbase;
        } else {
            src  = (part == 2 ? Bh : Bl) + (size_t)(n0 + rid) * K + k0 + c * 8;
            cc   = c + (part == 2 ? 0 : 4);
            base = sbase + BM * 128;
        }
        cp16(base + rid * 128 + ((cc ^ (rid & 7)) << 4), src);
    }
}

// ------------------------------ GEMM kernel --------------------------------
// MODE 0: Cf = acc + bias                (fp32 out)
// MODE 1: v  = acc + bias + temb[m>>3]   -> (Ch, Cl) bf16 pair out
template<int MODE>
__global__ __launch_bounds__(256)
void gemm_mma(const __nv_bfloat16* __restrict__ Ah, const __nv_bfloat16* __restrict__ Al,
              const __nv_bfloat16* __restrict__ Bh, const __nv_bfloat16* __restrict__ Bl,
              const float* __restrict__ bias, const float* __restrict__ temb,
              float* __restrict__ Cf,
              __nv_bfloat16* __restrict__ Ch, __nv_bfloat16* __restrict__ Cl,
              int M, int N, int K)
{
    extern __shared__ __align__(128) char smem[];
    const uint32_t sb = smem_u32(smem);

    const int tid  = threadIdx.x;
    const int wid  = tid >> 5;
    const int lane = tid & 31;
    const int warp_m = wid & 1;        // 2 warps over M (64 each)
    const int warp_n = wid >> 1;       // 4 warps over N (32 each)
    const int m0 = blockIdx.y * BM;
    const int n0 = blockIdx.x * BN;

    float acc[4][4][4];
#pragma unroll
    for (int a = 0; a < 4; a++)
#pragma unroll
        for (int b = 0; b < 4; b++)
#pragma unroll
            for (int c = 0; c < 4; c++) acc[a][b][c] = 0.0f;

    const int KT = K / BK;

    stage_copy(Ah, Al, Bh, Bl, K, m0, n0, 0, sb, tid);
    CP_COMMIT();
    stage_copy(Ah, Al, Bh, Bl, K, m0, n0, BK, sb + STAGE_BYTES, tid);
    CP_COMMIT();

    const int lr = lane & 15;          // ldmatrix row within 16
    const int lc = lane >> 4;          // 16B chunk select (0/1) within k16

#pragma unroll 1
    for (int kt = 0; kt < KT; kt++) {
        CP_WAIT1();
        __syncthreads();

        if (kt + 2 < KT)
            stage_copy(Ah, Al, Bh, Bl, K, m0, n0, (kt + 2) * BK,
                       sb + ((kt + 2) % NSTAGE) * STAGE_BYTES, tid);
        CP_COMMIT();

        const uint32_t as = sb + (kt % NSTAGE) * STAGE_BYTES;
        const uint32_t bs = as + BM * 128;

#pragma unroll
        for (int ks = 0; ks < 2; ks++) {
            uint32_t bh[4][2], bl[4][2];
#pragma unroll
            for (int p = 0; p < 2; p++) {
                const int r = warp_n * 32 + p * 16 + lr;
                const int ch = ks * 2 + lc;
                uint32_t r0, r1, r2, r3;
                ldsm_x4(r0, r1, r2, r3, bs + r * 128 + ((ch ^ (r & 7)) << 4));
                bh[2 * p][0] = r0; bh[2 * p][1] = r2;
                bh[2 * p + 1][0] = r1; bh[2 * p + 1][1] = r3;
                const int cl = ch + 4;
                ldsm_x4(r0, r1, r2, r3, bs + r * 128 + ((cl ^ (r & 7)) << 4));
                bl[2 * p][0] = r0; bl[2 * p][1] = r2;
                bl[2 * p + 1][0] = r1; bl[2 * p + 1][1] = r3;
            }
#pragma unroll
            for (int mf = 0; mf < 4; mf++) {
                const int r = warp_m * 64 + mf * 16 + lr;
                const int ch = ks * 2 + lc;
                uint32_t aH[4], aL[4];
                ldsm_x4(aH[0], aH[1], aH[2], aH[3],
                        as + r * 128 + ((ch ^ (r & 7)) << 4));
                ldsm_x4(aL[0], aL[1], aL[2], aL[3],
                        as + r * 128 + (((ch + 4) ^ (r & 7)) << 4));
#pragma unroll
                for (int nf = 0; nf < 4; nf++) {
                    mma16816(acc[mf][nf], aH, bh[nf]);
                    mma16816(acc[mf][nf], aH, bl[nf]);
                    mma16816(acc[mf][nf], aL, bh[nf]);
                }
            }
        }
    }

    // ------------------------------- epilogue ------------------------------
#pragma unroll
    for (int mf = 0; mf < 4; mf++)
#pragma unroll
        for (int nf = 0; nf < 4; nf++) {
            const int m = m0 + warp_m * 64 + mf * 16 + (lane >> 2);
            const int n = n0 + warp_n * 32 + nf * 8 + 2 * (lane & 3);
            const float* a = acc[mf][nf];
            const float b0 = bias[n], b1 = bias[n + 1];
            if (MODE == 0) {
                float2 v0 = make_float2(a[0] + b0, a[1] + b1);
                float2 v1 = make_float2(a[2] + b0, a[3] + b1);
                *reinterpret_cast<float2*>(Cf + (size_t)m * N + n) = v0;
                *reinterpret_cast<float2*>(Cf + (size_t)(m + 8) * N + n) = v1;
            } else {
#pragma unroll
                for (int rr = 0; rr < 2; rr++) {
                    const int mm = m + rr * 8;
                    const float* tp = temb + (size_t)(mm >> 3) * OUT_CH + n;
                    const float v0 = a[rr * 2 + 0] + b0 + tp[0];
                    const float v1 = a[rr * 2 + 1] + b1 + tp[1];
                    __nv_bfloat16 h0 = __float2bfloat16(v0);
                    __nv_bfloat16 h1 = __float2bfloat16(v1);
                    __nv_bfloat16 l0 = __float2bfloat16(v0 - __bfloat162float(h0));
                    __nv_bfloat16 l1 = __float2bfloat16(v1 - __bfloat162float(h1));
                    *reinterpret_cast<__nv_bfloat162*>(Ch + (size_t)mm * N + n) =
                        __halves2bfloat162(h0, h1);
                    *reinterpret_cast<__nv_bfloat162*>(Cl + (size_t)mm * N + n) =
                        __halves2bfloat162(l0, l1);
                }
            }
        }
}

// --------------------------- fp32 -> bf16 hi/lo ----------------------------
__global__ __launch_bounds__(256)
void cvt_pair(const float* __restrict__ s, __nv_bfloat16* __restrict__ h,
              __nv_bfloat16* __restrict__ l, int n)
{
    int i = (blockIdx.x * 256 + threadIdx.x) * 4;
    if (i >= n) return;
    float4 v = *reinterpret_cast<const float4*>(s + i);
    __nv_bfloat16 h0 = __float2bfloat16(v.x), h1 = __float2bfloat16(v.y);
    __nv_bfloat16 h2 = __float2bfloat16(v.z), h3 = __float2bfloat16(v.w);
    __nv_bfloat16 l0 = __float2bfloat16(v.x - __bfloat162float(h0));
    __nv_bfloat16 l1 = __float2bfloat16(v.y - __bfloat162float(h1));
    __nv_bfloat16 l2 = __float2bfloat16(v.z - __bfloat162float(h2));
    __nv_bfloat16 l3 = __float2bfloat16(v.w - __bfloat162float(h3));
    __nv_bfloat162 ha = __halves2bfloat162(h0, h1), hb = __halves2bfloat162(h2, h3);
    __nv_bfloat162 la = __halves2bfloat162(l0, l1), lb = __halves2bfloat162(l2, l3);
    *reinterpret_cast<uint2*>(h + i) =
        make_uint2(*reinterpret_cast<uint32_t*>(&ha), *reinterpret_cast<uint32_t*>(&hb));
    *reinterpret_cast<uint2*>(l + i) =
        make_uint2(*reinterpret_cast<uint32_t*>(&la), *reinterpret_cast<uint32_t*>(&lb));
}

// ------------------------------ attention ----------------------------------
__global__ __launch_bounds__(256)
void attn_kernel(const float* __restrict__ qkv,
                 __nv_bfloat16* __restrict__ oh, __nv_bfloat16* __restrict__ ol)
{
    __shared__ float s[8 * QKV_CH];
    const int tid = threadIdx.x;
    const size_t row0 = (size_t)blockIdx.x * 8;

    const float4* src = reinterpret_cast<const float4*>(qkv + row0 * QKV_CH);
    float4* dst = reinterpret_cast<float4*>(s);
#pragma unroll
    for (int i = 0; i < 12; i++) dst[tid + i * 256] = src[tid + i * 256];
    __syncthreads();

    const int warp = tid >> 5;
    const int lane = tid & 31;
    const float* qs = s + warp * QKV_CH;
    const float* ks = qs + 512;
    const float* vs = qs + 1024;
    const int i  = lane & 7;
    const int c0 = (lane >> 3) * 16;

    float qreg[16];
#pragma unroll
    for (int c = 0; c < 16; c++) qreg[c] = qs[i * 64 + c0 + c];

    float w[8];
#pragma unroll
    for (int j = 0; j < 8; j++) {
        float acc = 0.0f;
#pragma unroll
        for (int c = 0; c < 16; c++)
            acc = fmaf(qreg[c], ks[j * 64 + c0 + c], acc);
        acc += __shfl_xor_sync(0xffffffffu, acc, 8);
        acc += __shfl_xor_sync(0xffffffffu, acc, 16);
        w[j] = acc * 0.125f;
    }

    float mx = w[0];
#pragma unroll
    for (int j = 1; j < 8; j++) mx = fmaxf(mx, w[j]);
    float sum = 0.0f;
#pragma unroll
    for (int j = 0; j < 8; j++) { w[j] = __expf(w[j] - mx); sum += w[j]; }
    const float inv = 1.0f / sum;

    float o[16];
#pragma unroll
    for (int c = 0; c < 16; c++) o[c] = 0.0f;
#pragma unroll
    for (int j = 0; j < 8; j++) {
        const float wj = w[j];
#pragma unroll
        for (int c = 0; c < 16; c++)
            o[c] = fmaf(wj, vs[j * 64 + c0 + c], o[c]);
    }

    const size_t base = (row0 + warp) * (size_t)OUT_CH + i * 64 + c0;
#pragma unroll
    for (int p = 0; p < 8; p++) {
        float v0 = o[2 * p] * inv, v1 = o[2 * p + 1] * inv;
        __nv_bfloat16 h0 = __float2bfloat16(v0), h1 = __float2bfloat16(v1);
        __nv_bfloat16 l0 = __float2bfloat16(v0 - __bfloat162float(h0));
        __nv_bfloat16 l1 = __float2bfloat16(v1 - __bfloat162float(h1));
        *reinterpret_cast<__nv_bfloat162*>(oh + base + 2 * p) = __halves2bfloat162(h0, h1);
        *reinterpret_cast<__nv_bfloat162*>(ol + base + 2 * p) = __halves2bfloat162(l0, l1);
    }
}

// ---------------------------------------------------------------------------
extern "C" void kernel_launch(void* const* d_in, const int* in_sizes, int n_in,
                              void* d_out, int out_size)
{
    const float* x      = (const float*)d_in[0];
    const float* t      = (const float*)d_in[1];
    const float* W_down = (const float*)d_in[2];
    const float* b_down = (const float*)d_in[3];
    const float* W_t    = (const float*)d_in[4];
    const float* b_t    = (const float*)d_in[5];
    const float* W_qkv  = (const float*)d_in[6];
    const float* b_qkv  = (const float*)d_in[7];
    const float* W_out  = (const float*)d_in[8];
    const float* b_out  = (const float*)d_in[9];
    float* out = (float*)d_out;

    __nv_bfloat16 *xh, *xl, *th, *tl, *Wdh, *Wdl, *Wth, *Wtl, *Wqh, *Wql, *Woh, *Wol;
    __nv_bfloat16 *yh, *yl, *ath, *atl;
    float *temb, *qkv;
    cudaGetSymbolAddress((void**)&xh,  g_xh);  cudaGetSymbolAddress((void**)&xl,  g_xl);
    cudaGetSymbolAddress((void**)&th,  g_th);  cudaGetSymbolAddress((void**)&tl,  g_tl);
    cudaGetSymbolAddress((void**)&Wdh, g_Wdh); cudaGetSymbolAddress((void**)&Wdl, g_Wdl);
    cudaGetSymbolAddress((void**)&Wth, g_Wth); cudaGetSymbolAddress((void**)&Wtl, g_Wtl);
    cudaGetSymbolAddress((void**)&Wqh, g_Wqh); cudaGetSymbolAddress((void**)&Wql, g_Wql);
    cudaGetSymbolAddress((void**)&Woh, g_Woh); cudaGetSymbolAddress((void**)&Wol, g_Wol);
    cudaGetSymbolAddress((void**)&temb, g_temb);
    cudaGetSymbolAddress((void**)&yh,  g_yh);  cudaGetSymbolAddress((void**)&yl,  g_yl);
    cudaGetSymbolAddress((void**)&qkv, g_qkv);
    cudaGetSymbolAddress((void**)&ath, g_ath); cudaGetSymbolAddress((void**)&atl, g_atl);

    cudaFuncSetAttribute(gemm_mma<0>, cudaFuncAttributeMaxDynamicSharedMemorySize, SMEM_BYTES);
    cudaFuncSetAttribute(gemm_mma<1>, cudaFuncAttributeMaxDynamicSharedMemorySize, SMEM_BYTES);

    // fp32 -> bf16 hi/lo conversions
    cvt_pair<<<N_ROWS * IN_CH / 1024, 256>>>(x, xh, xl, N_ROWS * IN_CH);
    cvt_pair<<<N_BATCH * T_DIM / 1024, 256>>>(t, th, tl, N_BATCH * T_DIM);
    cvt_pair<<<OUT_CH * IN_CH / 1024, 256>>>(W_down, Wdh, Wdl, OUT_CH * IN_CH);
    cvt_pair<<<OUT_CH * T_DIM / 1024, 256>>>(W_t, Wth, Wtl, OUT_CH * T_DIM);
    cvt_pair<<<QKV_CH * OUT_CH / 1024, 256>>>(W_qkv, Wqh, Wql, QKV_CH * OUT_CH);
    cvt_pair<<<OUT_CH * OUT_CH / 1024, 256>>>(W_out, Woh, Wol, OUT_CH * OUT_CH);

    // temb = t @ W_t^T + b_t                       [8192, 512] fp32
    gemm_mma<0><<<dim3(OUT_CH / BN, N_BATCH / BM), 256, SMEM_BYTES>>>(
        th, tl, Wth, Wtl, b_t, nullptr, temb, nullptr, nullptr,
        N_BATCH, OUT_CH, T_DIM);

    // y = x @ W_down^T + b_down + temb[m>>3]       -> bf16 pair
    gemm_mma<1><<<dim3(OUT_CH / BN, N_ROWS / BM), 256, SMEM_BYTES>>>(
        xh, xl, Wdh, Wdl, b_down, temb, nullptr, yh, yl,
        N_ROWS, OUT_CH, IN_CH);

    // qkv = y @ W_qkv^T + b_qkv                    [65536, 1536] fp32
    gemm_mma<0><<<dim3(QKV_CH / BN, N_ROWS / BM), 256, SMEM_BYTES>>>(
        yh, yl, Wqh, Wql, b_qkv, nullptr, qkv, nullptr, nullptr,
        N_ROWS, QKV_CH, OUT_CH);

    // att = rowwise attention(qkv)                 -> bf16 pair
    attn_kernel<<<N_ROWS / 8, 256>>>(qkv, ath, atl);

    // out = att @ W_out^T + b_out                  [65536, 512] fp32
    gemm_mma<0><<<dim3(OUT_CH / BN, N_ROWS / BM), 256, SMEM_BYTES>>>(
        ath, atl, Woh, Wol, b_out, nullptr, out, nullptr, nullptr,
        N_ROWS, OUT_CH, OUT_CH);
}

// round 4
// speedup vs baseline: 1.5975x; 1.0123x over previous
#include <cuda_runtime.h>
#include <cuda_bf16.h>
#include <cstdint>

// ---------------------------------------------------------------------------
// TSABlock — mma.sync bf16 hi/lo 3-term GEMMs, 64x64 warp tiles (Round 4)
// ---------------------------------------------------------------------------

#define N_ROWS   65536
#define N_BATCH  8192
#define IN_CH    1024
#define OUT_CH   512
#define T_DIM    512
#define QKV_CH   1536

#define BM 128
#define BN 128
#define BK 32
static constexpr int STAGE_BYTES = (BM + BN) * 128;       // 32 KB
static constexpr int NSTAGE = 3;
static constexpr int SMEM_BYTES = NSTAGE * STAGE_BYTES;   // 96 KB

// ------------------------- device scratch (no cudaMalloc) -------------------
__device__ __align__(16) __nv_bfloat16 g_xh [N_ROWS * IN_CH];
__device__ __align__(16) __nv_bfloat16 g_xl [N_ROWS * IN_CH];
__device__ __align__(16) __nv_bfloat16 g_th [N_BATCH * T_DIM];
__device__ __align__(16) __nv_bfloat16 g_tl [N_BATCH * T_DIM];
__device__ __align__(16) __nv_bfloat16 g_Wdh[OUT_CH * IN_CH];
__device__ __align__(16) __nv_bfloat16 g_Wdl[OUT_CH * IN_CH];
__device__ __align__(16) __nv_bfloat16 g_Wth[OUT_CH * T_DIM];
__device__ __align__(16) __nv_bfloat16 g_Wtl[OUT_CH * T_DIM];
__device__ __align__(16) __nv_bfloat16 g_Wqh[QKV_CH * OUT_CH];
__device__ __align__(16) __nv_bfloat16 g_Wql[QKV_CH * OUT_CH];
__device__ __align__(16) __nv_bfloat16 g_Woh[OUT_CH * OUT_CH];
__device__ __align__(16) __nv_bfloat16 g_Wol[OUT_CH * OUT_CH];
__device__ __align__(16) float         g_temb[N_BATCH * OUT_CH];
__device__ __align__(16) __nv_bfloat16 g_yh [N_ROWS * OUT_CH];
__device__ __align__(16) __nv_bfloat16 g_yl [N_ROWS * OUT_CH];
__device__ __align__(16) float         g_qkv[N_ROWS * QKV_CH];
__device__ __align__(16) __nv_bfloat16 g_ath[N_ROWS * OUT_CH];
__device__ __align__(16) __nv_bfloat16 g_atl[N_ROWS * OUT_CH];

// ------------------------------ PTX helpers --------------------------------
__device__ __forceinline__ uint32_t smem_u32(const void* p) {
    uint32_t a;
    asm("{ .reg .u64 t; cvta.to.shared.u64 t, %1; cvt.u32.u64 %0, t; }"
        : "=r"(a) : "l"(p));
    return a;
}
#define CP_COMMIT() asm volatile("cp.async.commit_group;" ::: "memory")
#define CP_WAIT1()  asm volatile("cp.async.wait_group 1;" ::: "memory")

__device__ __forceinline__ void cp16(uint32_t dst, const void* src) {
    asm volatile("cp.async.cg.shared.global [%0], [%1], 16;" :: "r"(dst), "l"(src));
}

__device__ __forceinline__ void ldsm_x4(uint32_t& r0, uint32_t& r1,
                                        uint32_t& r2, uint32_t& r3, uint32_t a) {
    asm volatile("ldmatrix.sync.aligned.m8n8.x4.shared.b16 {%0,%1,%2,%3}, [%4];"
                 : "=r"(r0), "=r"(r1), "=r"(r2), "=r"(r3) : "r"(a));
}

__device__ __forceinline__ void mma16816(float* d, const uint32_t* a, const uint32_t* b) {
    asm volatile(
        "mma.sync.aligned.m16n8k16.row.col.f32.bf16.bf16.f32 "
        "{%0,%1,%2,%3}, {%4,%5,%6,%7}, {%8,%9}, {%0,%1,%2,%3};"
        : "+f"(d[0]), "+f"(d[1]), "+f"(d[2]), "+f"(d[3])
        : "r"(a[0]), "r"(a[1]), "r"(a[2]), "r"(a[3]), "r"(b[0]), "r"(b[1]));
}

// ------------------------------ stage copy ---------------------------------
// smem row = 128 B: [hi k0..31 | lo k0..31] bf16, XOR 16B-chunk swizzle.
__device__ __forceinline__ void stage_copy(
    const __nv_bfloat16* __restrict__ Ah, const __nv_bfloat16* __restrict__ Al,
    const __nv_bfloat16* __restrict__ Bh, const __nv_bfloat16* __restrict__ Bl,
    int K, int m0, int n0, int k0, uint32_t sbase, int tid)
{
#pragma unroll
    for (int i = 0; i < 16; i++) {
        int id   = tid + i * 128;          // 0..2047
        int part = id >> 9;                // 0 Ahi, 1 Alo, 2 Bhi, 3 Blo
        int rid  = (id >> 2) & 127;
        int c    = id & 3;
        const __nv_bfloat16* src;
        uint32_t base;
        int cc;
        if (part < 2) {
            src  = (part == 0 ? Ah : Al) + (size_t)(m0 + rid) * K + k0 + c * 8;
            cc   = c + (part == 0 ? 0 : 4);
            base = sbase;
        } else {
            src  = (part == 2 ? Bh : Bl) + (size_t)(n0 + rid) * K + k0 + c * 8;
            cc   = c + (part == 2 ? 0 : 4);
            base = sbase + BM * 128;
        }
        cp16(base + rid * 128 + ((cc ^ (rid & 7)) << 4), src);
    }
}

// ------------------------------ GEMM kernel --------------------------------
// 128 threads, 4 warps in 2x2 grid, warp tile 64x64.
// MODE 0: Cf = acc + bias                (fp32 out)
// MODE 1: v  = acc + bias + temb[m>>3]   -> (Ch, Cl) bf16 pair out
template<int MODE>
__global__ __launch_bounds__(128, 2)
void gemm_mma(const __nv_bfloat16* __restrict__ Ah, const __nv_bfloat16* __restrict__ Al,
              const __nv_bfloat16* __restrict__ Bh, const __nv_bfloat16* __restrict__ Bl,
              const float* __restrict__ bias, const float* __restrict__ temb,
              float* __restrict__ Cf,
              __nv_bfloat16* __restrict__ Ch, __nv_bfloat16* __restrict__ Cl,
              int M, int N, int K)
{
    extern __shared__ __align__(128) char smem[];
    const uint32_t sb = smem_u32(smem);

    const int tid  = threadIdx.x;
    const int wid  = tid >> 5;
    const int lane = tid & 31;
    const int warp_m = wid & 1;        // 2 warps over M (64 each)
    const int warp_n = wid >> 1;       // 2 warps over N (64 each)
    const int m0 = blockIdx.y * BM;
    const int n0 = blockIdx.x * BN;

    float acc[4][8][4];
#pragma unroll
    for (int a = 0; a < 4; a++)
#pragma unroll
        for (int b = 0; b < 8; b++)
#pragma unroll
            for (int c = 0; c < 4; c++) acc[a][b][c] = 0.0f;

    const int KT = K / BK;

    stage_copy(Ah, Al, Bh, Bl, K, m0, n0, 0, sb, tid);
    CP_COMMIT();
    stage_copy(Ah, Al, Bh, Bl, K, m0, n0, BK, sb + STAGE_BYTES, tid);
    CP_COMMIT();

    const int lr = lane & 15;          // ldmatrix row within 16
    const int lc = lane >> 4;          // 16B chunk select within k16

#pragma unroll 1
    for (int kt = 0; kt < KT; kt++) {
        CP_WAIT1();
        __syncthreads();

        if (kt + 2 < KT)
            stage_copy(Ah, Al, Bh, Bl, K, m0, n0, (kt + 2) * BK,
                       sb + ((kt + 2) % NSTAGE) * STAGE_BYTES, tid);
        CP_COMMIT();

        const uint32_t as = sb + (kt % NSTAGE) * STAGE_BYTES;
        const uint32_t bs = as + BM * 128;

#pragma unroll
        for (int ks = 0; ks < 2; ks++) {
            const int ch = ks * 2 + lc;
            uint32_t bh[8][2], bl[8][2];
#pragma unroll
            for (int p = 0; p < 4; p++) {
                const int r = warp_n * 64 + p * 16 + lr;
                uint32_t r0, r1, r2, r3;
                ldsm_x4(r0, r1, r2, r3, bs + r * 128 + ((ch ^ (r & 7)) << 4));
                bh[2 * p][0] = r0; bh[2 * p][1] = r2;
                bh[2 * p + 1][0] = r1; bh[2 * p + 1][1] = r3;
                ldsm_x4(r0, r1, r2, r3, bs + r * 128 + (((ch + 4) ^ (r & 7)) << 4));
                bl[2 * p][0] = r0; bl[2 * p][1] = r2;
                bl[2 * p + 1][0] = r1; bl[2 * p + 1][1] = r3;
            }
#pragma unroll
            for (int mf = 0; mf < 4; mf++) {
                const int r = warp_m * 64 + mf * 16 + lr;
                uint32_t aH[4], aL[4];
                ldsm_x4(aH[0], aH[1], aH[2], aH[3],
                        as + r * 128 + ((ch ^ (r & 7)) << 4));
                ldsm_x4(aL[0], aL[1], aL[2], aL[3],
                        as + r * 128 + (((ch + 4) ^ (r & 7)) << 4));
#pragma unroll
                for (int nf = 0; nf < 8; nf++) {
                    mma16816(acc[mf][nf], aH, bh[nf]);
                    mma16816(acc[mf][nf], aH, bl[nf]);
                    mma16816(acc[mf][nf], aL, bh[nf]);
                }
            }
        }
    }

    // ------------------------------- epilogue ------------------------------
#pragma unroll
    for (int mf = 0; mf < 4; mf++)
#pragma unroll
        for (int nf = 0; nf < 8; nf++) {
            const int m = m0 + warp_m * 64 + mf * 16 + (lane >> 2);
            const int n = n0 + warp_n * 64 + nf * 8 + 2 * (lane & 3);
            const float* a = acc[mf][nf];
            const float b0 = bias[n], b1 = bias[n + 1];
            if (MODE == 0) {
                float2 v0 = make_float2(a[0] + b0, a[1] + b1);
                float2 v1 = make_float2(a[2] + b0, a[3] + b1);
                *reinterpret_cast<float2*>(Cf + (size_t)m * N + n) = v0;
                *reinterpret_cast<float2*>(Cf + (size_t)(m + 8) * N + n) = v1;
            } else {
#pragma unroll
                for (int rr = 0; rr < 2; rr++) {
                    const int mm = m + rr * 8;
                    const float* tp = temb + (size_t)(mm >> 3) * OUT_CH + n;
                    const float v0 = a[rr * 2 + 0] + b0 + tp[0];
                    const float v1 = a[rr * 2 + 1] + b1 + tp[1];
                    __nv_bfloat16 h0 = __float2bfloat16(v0);
                    __nv_bfloat16 h1 = __float2bfloat16(v1);
                    __nv_bfloat16 l0 = __float2bfloat16(v0 - __bfloat162float(h0));
                    __nv_bfloat16 l1 = __float2bfloat16(v1 - __bfloat162float(h1));
                    *reinterpret_cast<__nv_bfloat162*>(Ch + (size_t)mm * N + n) =
                        __halves2bfloat162(h0, h1);
                    *reinterpret_cast<__nv_bfloat162*>(Cl + (size_t)mm * N + n) =
                        __halves2bfloat162(l0, l1);
                }
            }
        }
}

// --------------------------- fp32 -> bf16 hi/lo (all tensors, one launch) ---
__device__ __forceinline__ void cvt4(const float* __restrict__ s,
                                     __nv_bfloat16* __restrict__ h,
                                     __nv_bfloat16* __restrict__ l, int i)
{
    float4 v = *reinterpret_cast<const float4*>(s + i);
    __nv_bfloat16 h0 = __float2bfloat16(v.x), h1 = __float2bfloat16(v.y);
    __nv_bfloat16 h2 = __float2bfloat16(v.z), h3 = __float2bfloat16(v.w);
    __nv_bfloat16 l0 = __float2bfloat16(v.x - __bfloat162float(h0));
    __nv_bfloat16 l1 = __float2bfloat16(v.y - __bfloat162float(h1));
    __nv_bfloat16 l2 = __float2bfloat16(v.z - __bfloat162float(h2));
    __nv_bfloat16 l3 = __float2bfloat16(v.w - __bfloat162float(h3));
    __nv_bfloat162 ha = __halves2bfloat162(h0, h1), hb = __halves2bfloat162(h2, h3);
    __nv_bfloat162 la = __halves2bfloat162(l0, l1), lb = __halves2bfloat162(l2, l3);
    *reinterpret_cast<uint2*>(h + i) =
        make_uint2(*reinterpret_cast<uint32_t*>(&ha), *reinterpret_cast<uint32_t*>(&hb));
    *reinterpret_cast<uint2*>(l + i) =
        make_uint2(*reinterpret_cast<uint32_t*>(&la), *reinterpret_cast<uint32_t*>(&lb));
}

static constexpr int SZ_X  = N_ROWS * IN_CH;      // 67108864
static constexpr int SZ_T  = N_BATCH * T_DIM;     //  4194304
static constexpr int SZ_WD = OUT_CH * IN_CH;      //   524288
static constexpr int SZ_WT = OUT_CH * T_DIM;      //   262144
static constexpr int SZ_WQ = QKV_CH * OUT_CH;     //   786432
static constexpr int SZ_WO = OUT_CH * OUT_CH;     //   262144
static constexpr int C0 = SZ_X,      C1 = C0 + SZ_T,  C2 = C1 + SZ_WD;
static constexpr int C3 = C2 + SZ_WT, C4 = C3 + SZ_WQ, C5 = C4 + SZ_WO;
static constexpr int CVT_BLOCKS = C5 / 4 / 256;

__global__ __launch_bounds__(256)
void cvt_all(const float* __restrict__ x,  const float* __restrict__ t,
             const float* __restrict__ Wd, const float* __restrict__ Wt,
             const float* __restrict__ Wq, const float* __restrict__ Wo,
             __nv_bfloat16* __restrict__ xh, __nv_bfloat16* __restrict__ xl,
             __nv_bfloat16* __restrict__ th, __nv_bfloat16* __restrict__ tl,
             __nv_bfloat16* __restrict__ Wdh, __nv_bfloat16* __restrict__ Wdl,
             __nv_bfloat16* __restrict__ Wth, __nv_bfloat16* __restrict__ Wtl,
             __nv_bfloat16* __restrict__ Wqh, __nv_bfloat16* __restrict__ Wql,
             __nv_bfloat16* __restrict__ Woh, __nv_bfloat16* __restrict__ Wol)
{
    int i = (blockIdx.x * 256 + threadIdx.x) * 4;
    if (i < C0)      cvt4(x,  xh,  xl,  i);
    else if (i < C1) cvt4(t,  th,  tl,  i - C0);
    else if (i < C2) cvt4(Wd, Wdh, Wdl, i - C1);
    else if (i < C3) cvt4(Wt, Wth, Wtl, i - C2);
    else if (i < C4) cvt4(Wq, Wqh, Wql, i - C3);
    else             cvt4(Wo, Woh, Wol, i - C4);
}

// ------------------------------ attention ----------------------------------
__global__ __launch_bounds__(256)
void attn_kernel(const float* __restrict__ qkv,
                 __nv_bfloat16* __restrict__ oh, __nv_bfloat16* __restrict__ ol)
{
    __shared__ float s[8 * QKV_CH];
    const int tid = threadIdx.x;
    const size_t row0 = (size_t)blockIdx.x * 8;

    const float4* src = reinterpret_cast<const float4*>(qkv + row0 * QKV_CH);
    float4* dst = reinterpret_cast<float4*>(s);
#pragma unroll
    for (int i = 0; i < 12; i++) dst[tid + i * 256] = src[tid + i * 256];
    __syncthreads();

    const int warp = tid >> 5;
    const int lane = tid & 31;
    const float* qs = s + warp * QKV_CH;
    const float* ks = qs + 512;
    const float* vs = qs + 1024;
    const int i  = lane & 7;
    const int c0 = (lane >> 3) * 16;

    float qreg[16];
#pragma unroll
    for (int c = 0; c < 16; c++) qreg[c] = qs[i * 64 + c0 + c];

    float w[8];
#pragma unroll
    for (int j = 0; j < 8; j++) {
        float acc = 0.0f;
#pragma unroll
        for (int c = 0; c < 16; c++)
            acc = fmaf(qreg[c], ks[j * 64 + c0 + c], acc);
        acc += __shfl_xor_sync(0xffffffffu, acc, 8);
        acc += __shfl_xor_sync(0xffffffffu, acc, 16);
        w[j] = acc * 0.125f;
    }

    float mx = w[0];
#pragma unroll
    for (int j = 1; j < 8; j++) mx = fmaxf(mx, w[j]);
    float sum = 0.0f;
#pragma unroll
    for (int j = 0; j < 8; j++) { w[j] = __expf(w[j] - mx); sum += w[j]; }
    const float inv = 1.0f / sum;

    float o[16];
#pragma unroll
    for (int c = 0; c < 16; c++) o[c] = 0.0f;
#pragma unroll
    for (int j = 0; j < 8; j++) {
        const float wj = w[j];
#pragma unroll
        for (int c = 0; c < 16; c++)
            o[c] = fmaf(wj, vs[j * 64 + c0 + c], o[c]);
    }

    const size_t base = (row0 + warp) * (size_t)OUT_CH + i * 64 + c0;
#pragma unroll
    for (int p = 0; p < 8; p++) {
        float v0 = o[2 * p] * inv, v1 = o[2 * p + 1] * inv;
        __nv_bfloat16 h0 = __float2bfloat16(v0), h1 = __float2bfloat16(v1);
        __nv_bfloat16 l0 = __float2bfloat16(v0 - __bfloat162float(h0));
        __nv_bfloat16 l1 = __float2bfloat16(v1 - __bfloat162float(h1));
        *reinterpret_cast<__nv_bfloat162*>(oh + base + 2 * p) = __halves2bfloat162(h0, h1);
        *reinterpret_cast<__nv_bfloat162*>(ol + base + 2 * p) = __halves2bfloat162(l0, l1);
    }
}

// ---------------------------------------------------------------------------
extern "C" void kernel_launch(void* const* d_in, const int* in_sizes, int n_in,
                              void* d_out, int out_size)
{
    const float* x      = (const float*)d_in[0];
    const float* t      = (const float*)d_in[1];
    const float* W_down = (const float*)d_in[2];
    const float* b_down = (const float*)d_in[3];
    const float* W_t    = (const float*)d_in[4];
    const float* b_t    = (const float*)d_in[5];
    const float* W_qkv  = (const float*)d_in[6];
    const float* b_qkv  = (const float*)d_in[7];
    const float* W_out  = (const float*)d_in[8];
    const float* b_out  = (const float*)d_in[9];
    float* out = (float*)d_out;

    __nv_bfloat16 *xh, *xl, *th, *tl, *Wdh, *Wdl, *Wth, *Wtl, *Wqh, *Wql, *Woh, *Wol;
    __nv_bfloat16 *yh, *yl, *ath, *atl;
    float *temb, *qkv;
    cudaGetSymbolAddress((void**)&xh,  g_xh);  cudaGetSymbolAddress((void**)&xl,  g_xl);
    cudaGetSymbolAddress((void**)&th,  g_th);  cudaGetSymbolAddress((void**)&tl,  g_tl);
    cudaGetSymbolAddress((void**)&Wdh, g_Wdh); cudaGetSymbolAddress((void**)&Wdl, g_Wdl);
    cudaGetSymbolAddress((void**)&Wth, g_Wth); cudaGetSymbolAddress((void**)&Wtl, g_Wtl);
    cudaGetSymbolAddress((void**)&Wqh, g_Wqh); cudaGetSymbolAddress((void**)&Wql, g_Wql);
    cudaGetSymbolAddress((void**)&Woh, g_Woh); cudaGetSymbolAddress((void**)&Wol, g_Wol);
    cudaGetSymbolAddress((void**)&temb, g_temb);
    cudaGetSymbolAddress((void**)&yh,  g_yh);  cudaGetSymbolAddress((void**)&yl,  g_yl);
    cudaGetSymbolAddress((void**)&qkv, g_qkv);
    cudaGetSymbolAddress((void**)&ath, g_ath); cudaGetSymbolAddress((void**)&atl, g_atl);

    cudaFuncSetAttribute(gemm_mma<0>, cudaFuncAttributeMaxDynamicSharedMemorySize, SMEM_BYTES);
    cudaFuncSetAttribute(gemm_mma<1>, cudaFuncAttributeMaxDynamicSharedMemorySize, SMEM_BYTES);

    // launch 0: all fp32 -> bf16 hi/lo conversions in one kernel
    cvt_all<<<CVT_BLOCKS, 256>>>(x, t, W_down, W_t, W_qkv, W_out,
                                 xh, xl, th, tl, Wdh, Wdl, Wth, Wtl,
                                 Wqh, Wql, Woh, Wol);

    // launch 1: temb = t @ W_t^T + b_t             [8192, 512] fp32
    gemm_mma<0><<<dim3(OUT_CH / BN, N_BATCH / BM), 128, SMEM_BYTES>>>(
        th, tl, Wth, Wtl, b_t, nullptr, temb, nullptr, nullptr,
        N_BATCH, OUT_CH, T_DIM);

    // launch 2: y = x @ W_down^T + b_down + temb   -> bf16 pair
    gemm_mma<1><<<dim3(OUT_CH / BN, N_ROWS / BM), 128, SMEM_BYTES>>>(
        xh, xl, Wdh, Wdl, b_down, temb, nullptr, yh, yl,
        N_ROWS, OUT_CH, IN_CH);

    // launch 3: qkv = y @ W_qkv^T + b_qkv          [65536, 1536] fp32
    gemm_mma<0><<<dim3(QKV_CH / BN, N_ROWS / BM), 128, SMEM_BYTES>>>(
        yh, yl, Wqh, Wql, b_qkv, nullptr, qkv, nullptr, nullptr,
        N_ROWS, QKV_CH, OUT_CH);

    // launch 4: att = rowwise attention(qkv)       -> bf16 pair
    attn_kernel<<<N_ROWS / 8, 256>>>(qkv, ath, atl);

    // launch 5 (ncu capture target): out = att @ W_out^T + b_out
    gemm_mma<0><<<dim3(OUT_CH / BN, N_ROWS / BM), 128, SMEM_BYTES>>>(
        ath, atl, Woh, Wol, b_out, nullptr, out, nullptr, nullptr,
        N_ROWS, OUT_CH, OUT_CH);
}

// round 5
// speedup vs baseline: 3.6121x; 2.2611x over previous
#include <cuda_runtime.h>
#include <cuda_bf16.h>
#include <cuda_fp16.h>
#include <cstdint>

// ---------------------------------------------------------------------------
// TSABlock — fp16 hi/lo 2-term mma.sync GEMMs (Round 5)
//   C = A @ B^T:  A (activations) single fp16 hi;  B (weights) fp16 hi/lo pair.
//   acc = Ah*Bh + Ah*Bl  (drop Al*Bh ~ 2^-12; gate is 1e-3)
// ---------------------------------------------------------------------------

#define N_ROWS   65536
#define N_BATCH  8192
#define IN_CH    1024
#define OUT_CH   512
#define T_DIM    512
#define QKV_CH   1536

#define BM 128
#define BN 128
#define BK 32
static constexpr int A_BYTES = BM * 64;            // 128 rows x 32 fp16
static constexpr int B_BYTES = BN * 128;           // 128 rows x (hi32|lo32) fp16
static constexpr int STAGE_BYTES = A_BYTES + B_BYTES;   // 24 KB
static constexpr int NSTAGE = 3;
static constexpr int SMEM_BYTES = NSTAGE * STAGE_BYTES; // 72 KB

// ------------------------- device scratch (no cudaMalloc) -------------------
__device__ __align__(16) __half g_xh [N_ROWS * IN_CH];
__device__ __align__(16) __half g_th [N_BATCH * T_DIM];
__device__ __align__(16) __half g_Wdh[OUT_CH * IN_CH];
__device__ __align__(16) __half g_Wdl[OUT_CH * IN_CH];
__device__ __align__(16) __half g_Wth[OUT_CH * T_DIM];
__device__ __align__(16) __half g_Wtl[OUT_CH * T_DIM];
__device__ __align__(16) __half g_Wqh[QKV_CH * OUT_CH];
__device__ __align__(16) __half g_Wql[QKV_CH * OUT_CH];
__device__ __align__(16) __half g_Woh[OUT_CH * OUT_CH];
__device__ __align__(16) __half g_Wol[OUT_CH * OUT_CH];
__device__ __align__(16) float  g_temb[N_BATCH * OUT_CH];
__device__ __align__(16) __half g_yh [N_ROWS * OUT_CH];
__device__ __align__(16) float  g_qkv[N_ROWS * QKV_CH];
__device__ __align__(16) __half g_ath[N_ROWS * OUT_CH];

// ------------------------------ PTX helpers --------------------------------
__device__ __forceinline__ uint32_t smem_u32(const void* p) {
    uint32_t a;
    asm("{ .reg .u64 t; cvta.to.shared.u64 t, %1; cvt.u32.u64 %0, t; }"
        : "=r"(a) : "l"(p));
    return a;
}
#define CP_COMMIT() asm volatile("cp.async.commit_group;" ::: "memory")
#define CP_WAIT1()  asm volatile("cp.async.wait_group 1;" ::: "memory")

__device__ __forceinline__ void cp16(uint32_t dst, const void* src) {
    asm volatile("cp.async.cg.shared.global [%0], [%1], 16;" :: "r"(dst), "l"(src));
}

__device__ __forceinline__ void ldsm_x4(uint32_t& r0, uint32_t& r1,
                                        uint32_t& r2, uint32_t& r3, uint32_t a) {
    asm volatile("ldmatrix.sync.aligned.m8n8.x4.shared.b16 {%0,%1,%2,%3}, [%4];"
                 : "=r"(r0), "=r"(r1), "=r"(r2), "=r"(r3) : "r"(a));
}

__device__ __forceinline__ void mma16816(float* d, const uint32_t* a, const uint32_t* b) {
    asm volatile(
        "mma.sync.aligned.m16n8k16.row.col.f32.f16.f16.f32 "
        "{%0,%1,%2,%3}, {%4,%5,%6,%7}, {%8,%9}, {%0,%1,%2,%3};"
        : "+f"(d[0]), "+f"(d[1]), "+f"(d[2]), "+f"(d[3])
        : "r"(a[0]), "r"(a[1]), "r"(a[2]), "r"(a[3]), "r"(b[0]), "r"(b[1]));
}

// ------------------------------ stage copy ---------------------------------
// A: 128 rows x 64 B (32 fp16), swizzle chunk c -> c ^ ((r>>1)&3)
// B: 128 rows x 128 B (hi|lo),  swizzle chunk cc -> cc ^ (r&7)
__device__ __forceinline__ void stage_copy(
    const __half* __restrict__ Ah,
    const __half* __restrict__ Bh, const __half* __restrict__ Bl,
    int K, int m0, int n0, int k0, uint32_t sbase, int tid)
{
#pragma unroll
    for (int i = 0; i < 12; i++) {
        int id = tid + i * 128;              // 0..1535
        if (id < 512) {                      // A region: 128 rows x 4 chunks
            int rid = id >> 2, c = id & 3;
            const __half* src = Ah + (size_t)(m0 + rid) * K + k0 + c * 8;
            cp16(sbase + rid * 64 + ((c ^ ((rid >> 1) & 3)) << 4), src);
        } else {                             // B region: 128 rows x 8 chunks
            int idb = id - 512;
            int ph  = idb >> 9;              // 0 hi, 1 lo
            int rid = (idb >> 2) & 127;
            int c   = idb & 3;
            const __half* src = (ph ? Bl : Bh) + (size_t)(n0 + rid) * K + k0 + c * 8;
            int cc = c + ph * 4;
            cp16(sbase + A_BYTES + rid * 128 + ((cc ^ (rid & 7)) << 4), src);
        }
    }
}

// ------------------------------ GEMM kernel --------------------------------
// 128 threads, 4 warps 2x2, warp tile 64x64.
// MODE 0: Cf = acc + bias               (fp32 out)
// MODE 1: Ch = half(acc + bias + temb[m>>3])
template<int MODE>
__global__ __launch_bounds__(128, 2)
void gemm_mma(const __half* __restrict__ Ah,
              const __half* __restrict__ Bh, const __half* __restrict__ Bl,
              const float* __restrict__ bias, const float* __restrict__ temb,
              float* __restrict__ Cf, __half* __restrict__ Ch,
              int M, int N, int K)
{
    extern __shared__ __align__(128) char smem[];
    const uint32_t sb = smem_u32(smem);

    const int tid  = threadIdx.x;
    const int wid  = tid >> 5;
    const int lane = tid & 31;
    const int warp_m = wid & 1;
    const int warp_n = wid >> 1;
    const int m0 = blockIdx.y * BM;
    const int n0 = blockIdx.x * BN;

    float acc[4][8][4];
#pragma unroll
    for (int a = 0; a < 4; a++)
#pragma unroll
        for (int b = 0; b < 8; b++)
#pragma unroll
            for (int c = 0; c < 4; c++) acc[a][b][c] = 0.0f;

    const int KT = K / BK;

    stage_copy(Ah, Bh, Bl, K, m0, n0, 0, sb, tid);
    CP_COMMIT();
    stage_copy(Ah, Bh, Bl, K, m0, n0, BK, sb + STAGE_BYTES, tid);
    CP_COMMIT();

    const int lr = lane & 15;
    const int lc = lane >> 4;

#pragma unroll 1
    for (int kt = 0; kt < KT; kt++) {
        CP_WAIT1();
        __syncthreads();

        if (kt + 2 < KT)
            stage_copy(Ah, Bh, Bl, K, m0, n0, (kt + 2) * BK,
                       sb + ((kt + 2) % NSTAGE) * STAGE_BYTES, tid);
        CP_COMMIT();

        const uint32_t as = sb + (kt % NSTAGE) * STAGE_BYTES;
        const uint32_t bs = as + A_BYTES;

#pragma unroll
        for (int ks = 0; ks < 2; ks++) {
            const int ch = ks * 2 + lc;              // 0..3
            // B fragments: hi + lo, 64 n-values
            uint32_t bh[8][2], bl[8][2];
#pragma unroll
            for (int p = 0; p < 4; p++) {
                const int r = warp_n * 64 + p * 16 + lr;
                uint32_t r0, r1, r2, r3;
                ldsm_x4(r0, r1, r2, r3, bs + r * 128 + ((ch ^ (r & 7)) << 4));
                bh[2 * p][0] = r0; bh[2 * p][1] = r2;
                bh[2 * p + 1][0] = r1; bh[2 * p + 1][1] = r3;
                ldsm_x4(r0, r1, r2, r3, bs + r * 128 + (((ch + 4) ^ (r & 7)) << 4));
                bl[2 * p][0] = r0; bl[2 * p][1] = r2;
                bl[2 * p + 1][0] = r1; bl[2 * p + 1][1] = r3;
            }
            // A fragments (hi only), 64 m-values
            uint32_t aH[4][4];
#pragma unroll
            for (int mf = 0; mf < 4; mf++) {
                const int r = warp_m * 64 + mf * 16 + lr;
                ldsm_x4(aH[mf][0], aH[mf][1], aH[mf][2], aH[mf][3],
                        as + r * 64 + ((ch ^ ((r >> 1) & 3)) << 4));
            }
#pragma unroll
            for (int mf = 0; mf < 4; mf++)
#pragma unroll
                for (int nf = 0; nf < 8; nf++) {
                    mma16816(acc[mf][nf], aH[mf], bh[nf]);
                    mma16816(acc[mf][nf], aH[mf], bl[nf]);
                }
        }
    }

    // ------------------------------- epilogue ------------------------------
#pragma unroll
    for (int mf = 0; mf < 4; mf++)
#pragma unroll
        for (int nf = 0; nf < 8; nf++) {
            const int m = m0 + warp_m * 64 + mf * 16 + (lane >> 2);
            const int n = n0 + warp_n * 64 + nf * 8 + 2 * (lane & 3);
            const float* a = acc[mf][nf];
            const float b0 = bias[n], b1 = bias[n + 1];
            if (MODE == 0) {
                float2 v0 = make_float2(a[0] + b0, a[1] + b1);
                float2 v1 = make_float2(a[2] + b0, a[3] + b1);
                *reinterpret_cast<float2*>(Cf + (size_t)m * N + n) = v0;
                *reinterpret_cast<float2*>(Cf + (size_t)(m + 8) * N + n) = v1;
            } else {
#pragma unroll
                for (int rr = 0; rr < 2; rr++) {
                    const int mm = m + rr * 8;
                    const float* tp = temb + (size_t)(mm >> 3) * OUT_CH + n;
                    const float v0 = a[rr * 2 + 0] + b0 + tp[0];
                    const float v1 = a[rr * 2 + 1] + b1 + tp[1];
                    *reinterpret_cast<__half2*>(Ch + (size_t)mm * N + n) =
                        __floats2half2_rn(v0, v1);
                }
            }
        }
}

// --------------------------- conversions (one launch) ----------------------
__device__ __forceinline__ void cvt4s(const float* __restrict__ s,
                                      __half* __restrict__ h, int i)
{
    float4 v = *reinterpret_cast<const float4*>(s + i);
    __half2 a = __floats2half2_rn(v.x, v.y);
    __half2 b = __floats2half2_rn(v.z, v.w);
    *reinterpret_cast<uint2*>(h + i) =
        make_uint2(*reinterpret_cast<uint32_t*>(&a), *reinterpret_cast<uint32_t*>(&b));
}
__device__ __forceinline__ void cvt4p(const float* __restrict__ s,
                                      __half* __restrict__ h,
                                      __half* __restrict__ l, int i)
{
    float4 v = *reinterpret_cast<const float4*>(s + i);
    __half h0 = __float2half_rn(v.x), h1 = __float2half_rn(v.y);
    __half h2 = __float2half_rn(v.z), h3 = __float2half_rn(v.w);
    __half l0 = __float2half_rn(v.x - __half2float(h0));
    __half l1 = __float2half_rn(v.y - __half2float(h1));
    __half l2 = __float2half_rn(v.z - __half2float(h2));
    __half l3 = __float2half_rn(v.w - __half2float(h3));
    __half2 ha = __halves2half2(h0, h1), hb = __halves2half2(h2, h3);
    __half2 la = __halves2half2(l0, l1), lb = __halves2half2(l2, l3);
    *reinterpret_cast<uint2*>(h + i) =
        make_uint2(*reinterpret_cast<uint32_t*>(&ha), *reinterpret_cast<uint32_t*>(&hb));
    *reinterpret_cast<uint2*>(l + i) =
        make_uint2(*reinterpret_cast<uint32_t*>(&la), *reinterpret_cast<uint32_t*>(&lb));
}

static constexpr int SZ_X  = N_ROWS * IN_CH;
static constexpr int SZ_T  = N_BATCH * T_DIM;
static constexpr int SZ_WD = OUT_CH * IN_CH;
static constexpr int SZ_WT = OUT_CH * T_DIM;
static constexpr int SZ_WQ = QKV_CH * OUT_CH;
static constexpr int SZ_WO = OUT_CH * OUT_CH;
static constexpr int C0 = SZ_X,       C1 = C0 + SZ_T,  C2 = C1 + SZ_WD;
static constexpr int C3 = C2 + SZ_WT, C4 = C3 + SZ_WQ, C5 = C4 + SZ_WO;
static constexpr int CVT_BLOCKS = C5 / 4 / 256;

__global__ __launch_bounds__(256)
void cvt_all(const float* __restrict__ x,  const float* __restrict__ t,
             const float* __restrict__ Wd, const float* __restrict__ Wt,
             const float* __restrict__ Wq, const float* __restrict__ Wo,
             __half* __restrict__ xh,  __half* __restrict__ th,
             __half* __restrict__ Wdh, __half* __restrict__ Wdl,
             __half* __restrict__ Wth, __half* __restrict__ Wtl,
             __half* __restrict__ Wqh, __half* __restrict__ Wql,
             __half* __restrict__ Woh, __half* __restrict__ Wol)
{
    int i = (blockIdx.x * 256 + threadIdx.x) * 4;
    if (i < C0)      cvt4s(x, xh, i);
    else if (i < C1) cvt4s(t, th, i - C0);
    else if (i < C2) cvt4p(Wd, Wdh, Wdl, i - C1);
    else if (i < C3) cvt4p(Wt, Wth, Wtl, i - C2);
    else if (i < C4) cvt4p(Wq, Wqh, Wql, i - C3);
    else             cvt4p(Wo, Woh, Wol, i - C4);
}

// ------------------------------ attention ----------------------------------
__global__ __launch_bounds__(256)
void attn_kernel(const float* __restrict__ qkv, __half* __restrict__ oh)
{
    __shared__ float s[8 * QKV_CH];
    const int tid = threadIdx.x;
    const size_t row0 = (size_t)blockIdx.x * 8;

    const float4* src = reinterpret_cast<const float4*>(qkv + row0 * QKV_CH);
    float4* dst = reinterpret_cast<float4*>(s);
#pragma unroll
    for (int i = 0; i < 12; i++) dst[tid + i * 256] = src[tid + i * 256];
    __syncthreads();

    const int warp = tid >> 5;
    const int lane = tid & 31;
    const float* qs = s + warp * QKV_CH;
    const float* ks = qs + 512;
    const float* vs = qs + 1024;
    const int i  = lane & 7;
    const int c0 = (lane >> 3) * 16;

    float qreg[16];
#pragma unroll
    for (int c = 0; c < 16; c++) qreg[c] = qs[i * 64 + c0 + c];

    float w[8];
#pragma unroll
    for (int j = 0; j < 8; j++) {
        float acc = 0.0f;
#pragma unroll
        for (int c = 0; c < 16; c++)
            acc = fmaf(qreg[c], ks[j * 64 + c0 + c], acc);
        acc += __shfl_xor_sync(0xffffffffu, acc, 8);
        acc += __shfl_xor_sync(0xffffffffu, acc, 16);
        w[j] = acc * 0.125f;
    }

    float mx = w[0];
#pragma unroll
    for (int j = 1; j < 8; j++) mx = fmaxf(mx, w[j]);
    float sum = 0.0f;
#pragma unroll
    for (int j = 0; j < 8; j++) { w[j] = __expf(w[j] - mx); sum += w[j]; }
    const float inv = 1.0f / sum;

    float o[16];
#pragma unroll
    for (int c = 0; c < 16; c++) o[c] = 0.0f;
#pragma unroll
    for (int j = 0; j < 8; j++) {
        const float wj = w[j];
#pragma unroll
        for (int c = 0; c < 16; c++)
            o[c] = fmaf(wj, vs[j * 64 + c0 + c], o[c]);
    }

    __half* op = oh + (row0 + warp) * (size_t)OUT_CH + i * 64 + c0;
    uint32_t pk[8];
#pragma unroll
    for (int p = 0; p < 8; p++) {
        __half2 h = __floats2half2_rn(o[2 * p] * inv, o[2 * p + 1] * inv);
        pk[p] = *reinterpret_cast<uint32_t*>(&h);
    }
    *reinterpret_cast<uint4*>(op)     = make_uint4(pk[0], pk[1], pk[2], pk[3]);
    *reinterpret_cast<uint4*>(op + 8) = make_uint4(pk[4], pk[5], pk[6], pk[7]);
}

// ---------------------------------------------------------------------------
extern "C" void kernel_launch(void* const* d_in, const int* in_sizes, int n_in,
                              void* d_out, int out_size)
{
    const float* x      = (const float*)d_in[0];
    const float* t      = (const float*)d_in[1];
    const float* W_down = (const float*)d_in[2];
    const float* b_down = (const float*)d_in[3];
    const float* W_t    = (const float*)d_in[4];
    const float* b_t    = (const float*)d_in[5];
    const float* W_qkv  = (const float*)d_in[6];
    const float* b_qkv  = (const float*)d_in[7];
    const float* W_out  = (const float*)d_in[8];
    const float* b_out  = (const float*)d_in[9];
    float* out = (float*)d_out;

    __half *xh, *th, *Wdh, *Wdl, *Wth, *Wtl, *Wqh, *Wql, *Woh, *Wol, *yh, *ath;
    float *temb, *qkv;
    cudaGetSymbolAddress((void**)&xh,  g_xh);
    cudaGetSymbolAddress((void**)&th,  g_th);
    cudaGetSymbolAddress((void**)&Wdh, g_Wdh); cudaGetSymbolAddress((void**)&Wdl, g_Wdl);
    cudaGetSymbolAddress((void**)&Wth, g_Wth); cudaGetSymbolAddress((void**)&Wtl, g_Wtl);
    cudaGetSymbolAddress((void**)&Wqh, g_Wqh); cudaGetSymbolAddress((void**)&Wql, g_Wql);
    cudaGetSymbolAddress((void**)&Woh, g_Woh); cudaGetSymbolAddress((void**)&Wol, g_Wol);
    cudaGetSymbolAddress((void**)&temb, g_temb);
    cudaGetSymbolAddress((void**)&yh,  g_yh);
    cudaGetSymbolAddress((void**)&qkv, g_qkv);
    cudaGetSymbolAddress((void**)&ath, g_ath);

    cudaFuncSetAttribute(gemm_mma<0>, cudaFuncAttributeMaxDynamicSharedMemorySize, SMEM_BYTES);
    cudaFuncSetAttribute(gemm_mma<1>, cudaFuncAttributeMaxDynamicSharedMemorySize, SMEM_BYTES);

    // launch 0: conversions
    cvt_all<<<CVT_BLOCKS, 256>>>(x, t, W_down, W_t, W_qkv, W_out,
                                 xh, th, Wdh, Wdl, Wth, Wtl, Wqh, Wql, Woh, Wol);

    // launch 1: temb = t @ W_t^T + b_t             [8192, 512] fp32
    gemm_mma<0><<<dim3(OUT_CH / BN, N_BATCH / BM), 128, SMEM_BYTES>>>(
        th, Wth, Wtl, b_t, nullptr, temb, nullptr, N_BATCH, OUT_CH, T_DIM);

    // launch 2: y = x @ W_down^T + b_down + temb   -> fp16
    gemm_mma<1><<<dim3(OUT_CH / BN, N_ROWS / BM), 128, SMEM_BYTES>>>(
        xh, Wdh, Wdl, b_down, temb, nullptr, yh, N_ROWS, OUT_CH, IN_CH);

    // launch 3: qkv = y @ W_qkv^T + b_qkv          [65536, 1536] fp32
    gemm_mma<0><<<dim3(QKV_CH / BN, N_ROWS / BM), 128, SMEM_BYTES>>>(
        yh, Wqh, Wql, b_qkv, nullptr, qkv, nullptr, N_ROWS, QKV_CH, OUT_CH);

    // launch 4: att = rowwise attention(qkv)       -> fp16
    attn_kernel<<<N_ROWS / 8, 256>>>(qkv, ath);

    // launch 5 (ncu capture target): out = att @ W_out^T + b_out
    gemm_mma<0><<<dim3(OUT_CH / BN, N_ROWS / BM), 128, SMEM_BYTES>>>(
        ath, Woh, Wol, b_out, nullptr, out, nullptr, N_ROWS, OUT_CH, OUT_CH);
}

// round 6
// speedup vs baseline: 5.5669x; 1.5412x over previous
#include <cuda_runtime.h>
#include <cuda_fp16.h>
#include <cstdint>

// ---------------------------------------------------------------------------
// TSABlock — single-fp16 mma.sync GEMMs, 4-stage cp.async (Round 6)
//   C = A @ B^T, everything fp16 in / fp32 accumulate.
// ---------------------------------------------------------------------------

#define N_ROWS   65536
#define N_BATCH  8192
#define IN_CH    1024
#define OUT_CH   512
#define T_DIM    512
#define QKV_CH   1536

#define BM 128
#define BN 128
#define BK 32
static constexpr int A_BYTES = BM * 64;                 // 8 KB
static constexpr int B_BYTES = BN * 64;                 // 8 KB
static constexpr int STAGE_BYTES = A_BYTES + B_BYTES;   // 16 KB
static constexpr int NSTAGE = 4;
static constexpr int SMEM_BYTES = NSTAGE * STAGE_BYTES; // 64 KB

// ------------------------- device scratch (no cudaMalloc) -------------------
__device__ __align__(16) __half g_xh [N_ROWS * IN_CH];
__device__ __align__(16) __half g_th [N_BATCH * T_DIM];
__device__ __align__(16) __half g_Wdh[OUT_CH * IN_CH];
__device__ __align__(16) __half g_Wth[OUT_CH * T_DIM];
__device__ __align__(16) __half g_Wqh[QKV_CH * OUT_CH];
__device__ __align__(16) __half g_Woh[OUT_CH * OUT_CH];
__device__ __align__(16) float  g_temb[N_BATCH * OUT_CH];
__device__ __align__(16) __half g_yh [N_ROWS * OUT_CH];
__device__ __align__(16) float  g_qkv[N_ROWS * QKV_CH];
__device__ __align__(16) __half g_ath[N_ROWS * OUT_CH];

// ------------------------------ PTX helpers --------------------------------
__device__ __forceinline__ uint32_t smem_u32(const void* p) {
    uint32_t a;
    asm("{ .reg .u64 t; cvta.to.shared.u64 t, %1; cvt.u32.u64 %0, t; }"
        : "=r"(a) : "l"(p));
    return a;
}
#define CP_COMMIT() asm volatile("cp.async.commit_group;" ::: "memory")
#define CP_WAIT2()  asm volatile("cp.async.wait_group 2;" ::: "memory")

__device__ __forceinline__ void cp16(uint32_t dst, const void* src) {
    asm volatile("cp.async.cg.shared.global [%0], [%1], 16;" :: "r"(dst), "l"(src));
}

__device__ __forceinline__ void ldsm_x4(uint32_t& r0, uint32_t& r1,
                                        uint32_t& r2, uint32_t& r3, uint32_t a) {
    asm volatile("ldmatrix.sync.aligned.m8n8.x4.shared.b16 {%0,%1,%2,%3}, [%4];"
                 : "=r"(r0), "=r"(r1), "=r"(r2), "=r"(r3) : "r"(a));
}

__device__ __forceinline__ void mma16816(float* d, const uint32_t* a, const uint32_t* b) {
    asm volatile(
        "mma.sync.aligned.m16n8k16.row.col.f32.f16.f16.f32 "
        "{%0,%1,%2,%3}, {%4,%5,%6,%7}, {%8,%9}, {%0,%1,%2,%3};"
        : "+f"(d[0]), "+f"(d[1]), "+f"(d[2]), "+f"(d[3])
        : "r"(a[0]), "r"(a[1]), "r"(a[2]), "r"(a[3]), "r"(b[0]), "r"(b[1]));
}

// ------------------------------ stage copy ---------------------------------
// A and B: 128 rows x 64 B (32 fp16), swizzle chunk c -> c ^ ((r>>1)&3)
__device__ __forceinline__ void stage_copy(
    const __half* __restrict__ Ah, const __half* __restrict__ Bh,
    int K, int m0, int n0, int k0, uint32_t sbase, int tid)
{
#pragma unroll
    for (int i = 0; i < 8; i++) {
        int id = tid + i * 128;              // 0..1023
        int rid = (id >> 2) & 127;
        int c   = id & 3;
        uint32_t off = rid * 64 + ((c ^ ((rid >> 1) & 3)) << 4);
        if (id < 512) {
            cp16(sbase + off, Ah + (size_t)(m0 + rid) * K + k0 + c * 8);
        } else {
            cp16(sbase + A_BYTES + off, Bh + (size_t)(n0 + rid) * K + k0 + c * 8);
        }
    }
}

// ------------------------------ GEMM kernel --------------------------------
// 128 threads, 4 warps 2x2, warp tile 64x64.
// MODE 0: Cf = acc + bias               (fp32 out)
// MODE 1: Ch = half(acc + bias + temb[m>>3])
template<int MODE>
__global__ __launch_bounds__(128, 2)
void gemm_mma(const __half* __restrict__ Ah, const __half* __restrict__ Bh,
              const float* __restrict__ bias, const float* __restrict__ temb,
              float* __restrict__ Cf, __half* __restrict__ Ch,
              int M, int N, int K)
{
    extern __shared__ __align__(128) char smem[];
    const uint32_t sb = smem_u32(smem);

    const int tid  = threadIdx.x;
    const int wid  = tid >> 5;
    const int lane = tid & 31;
    const int warp_m = wid & 1;
    const int warp_n = wid >> 1;
    const int m0 = blockIdx.y * BM;
    const int n0 = blockIdx.x * BN;

    float acc[4][8][4];
#pragma unroll
    for (int a = 0; a < 4; a++)
#pragma unroll
        for (int b = 0; b < 8; b++)
#pragma unroll
            for (int c = 0; c < 4; c++) acc[a][b][c] = 0.0f;

    const int KT = K / BK;

    // prologue: 3 stages in flight
    stage_copy(Ah, Bh, K, m0, n0, 0, sb, tid);
    CP_COMMIT();
    stage_copy(Ah, Bh, K, m0, n0, BK, sb + STAGE_BYTES, tid);
    CP_COMMIT();
    stage_copy(Ah, Bh, K, m0, n0, 2 * BK, sb + 2 * STAGE_BYTES, tid);
    CP_COMMIT();

    const int lr = lane & 15;
    const int lc = lane >> 4;

    // precomputed swizzled ldmatrix offsets: [ks][frag]
    uint32_t aOff[2][4], bOff[2][4];
#pragma unroll
    for (int ks = 0; ks < 2; ks++) {
        const int ch = ks * 2 + lc;
#pragma unroll
        for (int f = 0; f < 4; f++) {
            const int ra = warp_m * 64 + f * 16 + lr;
            const int rb = warp_n * 64 + f * 16 + lr;
            aOff[ks][f] = ra * 64 + ((ch ^ ((ra >> 1) & 3)) << 4);
            bOff[ks][f] = A_BYTES + rb * 64 + ((ch ^ ((rb >> 1) & 3)) << 4);
        }
    }

#pragma unroll 1
    for (int kt = 0; kt < KT; kt++) {
        CP_WAIT2();
        __syncthreads();

        if (kt + 3 < KT)
            stage_copy(Ah, Bh, K, m0, n0, (kt + 3) * BK,
                       sb + ((kt + 3) % NSTAGE) * STAGE_BYTES, tid);
        CP_COMMIT();

        const uint32_t st = sb + (kt % NSTAGE) * STAGE_BYTES;

#pragma unroll
        for (int ks = 0; ks < 2; ks++) {
            uint32_t bh[8][2];
#pragma unroll
            for (int p = 0; p < 4; p++) {
                uint32_t r0, r1, r2, r3;
                ldsm_x4(r0, r1, r2, r3, st + bOff[ks][p]);
                bh[2 * p][0] = r0; bh[2 * p][1] = r2;
                bh[2 * p + 1][0] = r1; bh[2 * p + 1][1] = r3;
            }
            uint32_t aH[4][4];
#pragma unroll
            for (int mf = 0; mf < 4; mf++)
                ldsm_x4(aH[mf][0], aH[mf][1], aH[mf][2], aH[mf][3],
                        st + aOff[ks][mf]);
#pragma unroll
            for (int mf = 0; mf < 4; mf++)
#pragma unroll
                for (int nf = 0; nf < 8; nf++)
                    mma16816(acc[mf][nf], aH[mf], bh[nf]);
        }
    }

    // ------------------------------- epilogue ------------------------------
#pragma unroll
    for (int mf = 0; mf < 4; mf++)
#pragma unroll
        for (int nf = 0; nf < 8; nf++) {
            const int m = m0 + warp_m * 64 + mf * 16 + (lane >> 2);
            const int n = n0 + warp_n * 64 + nf * 8 + 2 * (lane & 3);
            const float* a = acc[mf][nf];
            const float b0 = bias[n], b1 = bias[n + 1];
            if (MODE == 0) {
                float2 v0 = make_float2(a[0] + b0, a[1] + b1);
                float2 v1 = make_float2(a[2] + b0, a[3] + b1);
                *reinterpret_cast<float2*>(Cf + (size_t)m * N + n) = v0;
                *reinterpret_cast<float2*>(Cf + (size_t)(m + 8) * N + n) = v1;
            } else {
#pragma unroll
                for (int rr = 0; rr < 2; rr++) {
                    const int mm = m + rr * 8;
                    const float* tp = temb + (size_t)(mm >> 3) * OUT_CH + n;
                    const float v0 = a[rr * 2 + 0] + b0 + tp[0];
                    const float v1 = a[rr * 2 + 1] + b1 + tp[1];
                    *reinterpret_cast<__half2*>(Ch + (size_t)mm * N + n) =
                        __floats2half2_rn(v0, v1);
                }
            }
        }
}

// --------------------------- conversions (one launch) ----------------------
__device__ __forceinline__ void cvt4s(const float* __restrict__ s,
                                      __half* __restrict__ h, int i)
{
    float4 v = *reinterpret_cast<const float4*>(s + i);
    __half2 a = __floats2half2_rn(v.x, v.y);
    __half2 b = __floats2half2_rn(v.z, v.w);
    *reinterpret_cast<uint2*>(h + i) =
        make_uint2(*reinterpret_cast<uint32_t*>(&a), *reinterpret_cast<uint32_t*>(&b));
}

static constexpr int SZ_X  = N_ROWS * IN_CH;
static constexpr int SZ_T  = N_BATCH * T_DIM;
static constexpr int SZ_WD = OUT_CH * IN_CH;
static constexpr int SZ_WT = OUT_CH * T_DIM;
static constexpr int SZ_WQ = QKV_CH * OUT_CH;
static constexpr int SZ_WO = OUT_CH * OUT_CH;
static constexpr int C0 = SZ_X,       C1 = C0 + SZ_T,  C2 = C1 + SZ_WD;
static constexpr int C3 = C2 + SZ_WT, C4 = C3 + SZ_WQ, C5 = C4 + SZ_WO;
static constexpr int CVT_BLOCKS = C5 / 4 / 256;

__global__ __launch_bounds__(256)
void cvt_all(const float* __restrict__ x,  const float* __restrict__ t,
             const float* __restrict__ Wd, const float* __restrict__ Wt,
             const float* __restrict__ Wq, const float* __restrict__ Wo,
             __half* __restrict__ xh,  __half* __restrict__ th,
             __half* __restrict__ Wdh, __half* __restrict__ Wth,
             __half* __restrict__ Wqh, __half* __restrict__ Woh)
{
    int i = (blockIdx.x * 256 + threadIdx.x) * 4;
    if (i < C0)      cvt4s(x,  xh,  i);
    else if (i < C1) cvt4s(t,  th,  i - C0);
    else if (i < C2) cvt4s(Wd, Wdh, i - C1);
    else if (i < C3) cvt4s(Wt, Wth, i - C2);
    else if (i < C4) cvt4s(Wq, Wqh, i - C3);
    else             cvt4s(Wo, Woh, i - C4);
}

// ------------------------------ attention ----------------------------------
__global__ __launch_bounds__(256)
void attn_kernel(const float* __restrict__ qkv, __half* __restrict__ oh)
{
    __shared__ float s[8 * QKV_CH];
    const int tid = threadIdx.x;
    const size_t row0 = (size_t)blockIdx.x * 8;

    const float4* src = reinterpret_cast<const float4*>(qkv + row0 * QKV_CH);
    float4* dst = reinterpret_cast<float4*>(s);
#pragma unroll
    for (int i = 0; i < 12; i++) dst[tid + i * 256] = src[tid + i * 256];
    __syncthreads();

    const int warp = tid >> 5;
    const int lane = tid & 31;
    const float* qs = s + warp * QKV_CH;
    const float* ks = qs + 512;
    const float* vs = qs + 1024;
    const int i  = lane & 7;
    const int c0 = (lane >> 3) * 16;

    float qreg[16];
#pragma unroll
    for (int c = 0; c < 16; c++) qreg[c] = qs[i * 64 + c0 + c];

    float w[8];
#pragma unroll
    for (int j = 0; j < 8; j++) {
        float acc = 0.0f;
#pragma unroll
        for (int c = 0; c < 16; c++)
            acc = fmaf(qreg[c], ks[j * 64 + c0 + c], acc);
        acc += __shfl_xor_sync(0xffffffffu, acc, 8);
        acc += __shfl_xor_sync(0xffffffffu, acc, 16);
        w[j] = acc * 0.125f;
    }

    float mx = w[0];
#pragma unroll
    for (int j = 1; j < 8; j++) mx = fmaxf(mx, w[j]);
    float sum = 0.0f;
#pragma unroll
    for (int j = 0; j < 8; j++) { w[j] = __expf(w[j] - mx); sum += w[j]; }
    const float inv = 1.0f / sum;

    float o[16];
#pragma unroll
    for (int c = 0; c < 16; c++) o[c] = 0.0f;
#pragma unroll
    for (int j = 0; j < 8; j++) {
        const float wj = w[j];
#pragma unroll
        for (int c = 0; c < 16; c++)
            o[c] = fmaf(wj, vs[j * 64 + c0 + c], o[c]);
    }

    __half* op = oh + (row0 + warp) * (size_t)OUT_CH + i * 64 + c0;
    uint32_t pk[8];
#pragma unroll
    for (int p = 0; p < 8; p++) {
        __half2 h = __floats2half2_rn(o[2 * p] * inv, o[2 * p + 1] * inv);
        pk[p] = *reinterpret_cast<uint32_t*>(&h);
    }
    *reinterpret_cast<uint4*>(op)     = make_uint4(pk[0], pk[1], pk[2], pk[3]);
    *reinterpret_cast<uint4*>(op + 8) = make_uint4(pk[4], pk[5], pk[6], pk[7]);
}

// ---------------------------------------------------------------------------
extern "C" void kernel_launch(void* const* d_in, const int* in_sizes, int n_in,
                              void* d_out, int out_size)
{
    const float* x      = (const float*)d_in[0];
    const float* t      = (const float*)d_in[1];
    const float* W_down = (const float*)d_in[2];
    const float* b_down = (const float*)d_in[3];
    const float* W_t    = (const float*)d_in[4];
    const float* b_t    = (const float*)d_in[5];
    const float* W_qkv  = (const float*)d_in[6];
    const float* b_qkv  = (const float*)d_in[7];
    const float* W_out  = (const float*)d_in[8];
    const float* b_out  = (const float*)d_in[9];
    float* out = (float*)d_out;

    __half *xh, *th, *Wdh, *Wth, *Wqh, *Woh, *yh, *ath;
    float *temb, *qkv;
    cudaGetSymbolAddress((void**)&xh,  g_xh);
    cudaGetSymbolAddress((void**)&th,  g_th);
    cudaGetSymbolAddress((void**)&Wdh, g_Wdh);
    cudaGetSymbolAddress((void**)&Wth, g_Wth);
    cudaGetSymbolAddress((void**)&Wqh, g_Wqh);
    cudaGetSymbolAddress((void**)&Woh, g_Woh);
    cudaGetSymbolAddress((void**)&temb, g_temb);
    cudaGetSymbolAddress((void**)&yh,  g_yh);
    cudaGetSymbolAddress((void**)&qkv, g_qkv);
    cudaGetSymbolAddress((void**)&ath, g_ath);

    cudaFuncSetAttribute(gemm_mma<0>, cudaFuncAttributeMaxDynamicSharedMemorySize, SMEM_BYTES);
    cudaFuncSetAttribute(gemm_mma<1>, cudaFuncAttributeMaxDynamicSharedMemorySize, SMEM_BYTES);

    // launch 0: conversions
    cvt_all<<<CVT_BLOCKS, 256>>>(x, t, W_down, W_t, W_qkv, W_out,
                                 xh, th, Wdh, Wth, Wqh, Woh);

    // launch 1: temb = t @ W_t^T + b_t             [8192, 512] fp32
    gemm_mma<0><<<dim3(OUT_CH / BN, N_BATCH / BM), 128, SMEM_BYTES>>>(
        th, Wth, b_t, nullptr, temb, nullptr, N_BATCH, OUT_CH, T_DIM);

    // launch 2: y = x @ W_down^T + b_down + temb   -> fp16
    gemm_mma<1><<<dim3(OUT_CH / BN, N_ROWS / BM), 128, SMEM_BYTES>>>(
        xh, Wdh, b_down, temb, nullptr, yh, N_ROWS, OUT_CH, IN_CH);

    // launch 3: qkv = y @ W_qkv^T + b_qkv          [65536, 1536] fp32
    gemm_mma<0><<<dim3(QKV_CH / BN, N_ROWS / BM), 128, SMEM_BYTES>>>(
        yh, Wqh, b_qkv, nullptr, qkv, nullptr, N_ROWS, QKV_CH, OUT_CH);

    // launch 4: att = rowwise attention(qkv)       -> fp16
    attn_kernel<<<N_ROWS / 8, 256>>>(qkv, ath);

    // launch 5 (ncu capture target): out = att @ W_out^T + b_out
    gemm_mma<0><<<dim3(OUT_CH / BN, N_ROWS / BM), 128, SMEM_BYTES>>>(
        ath, Woh, b_out, nullptr, out, nullptr, N_ROWS, OUT_CH, OUT_CH);
}

// round 8
// speedup vs baseline: 6.7697x; 1.2161x over previous
#include <cuda_runtime.h>
#include <cuda_fp16.h>
#include <cstdint>

// ---------------------------------------------------------------------------
// TSABlock — fp16 mma.sync GEMMs with fragment double-buffering (Round 7)
// ---------------------------------------------------------------------------

#define N_ROWS   65536
#define N_BATCH  8192
#define IN_CH    1024
#define OUT_CH   512
#define T_DIM    512
#define QKV_CH   1536

#define BM 128
#define BN 128
#define BK 32
static constexpr int A_BYTES = BM * 64;                 // 8 KB
static constexpr int B_BYTES = BN * 64;                 // 8 KB
static constexpr int STAGE_BYTES = A_BYTES + B_BYTES;   // 16 KB
static constexpr int NSTAGE = 4;
static constexpr int SMEM_BYTES = NSTAGE * STAGE_BYTES; // 64 KB

// ------------------------- device scratch (no cudaMalloc) -------------------
__device__ __align__(16) __half g_xh  [N_ROWS * IN_CH];
__device__ __align__(16) __half g_th  [N_BATCH * T_DIM];
__device__ __align__(16) __half g_Wdh [OUT_CH * IN_CH];
__device__ __align__(16) __half g_Wth [OUT_CH * T_DIM];
__device__ __align__(16) __half g_Wqh [QKV_CH * OUT_CH];
__device__ __align__(16) __half g_Woh [OUT_CH * OUT_CH];
__device__ __align__(16) float  g_temb[N_BATCH * OUT_CH];
__device__ __align__(16) __half g_yh  [N_ROWS * OUT_CH];
__device__ __align__(16) __half g_qkvh[N_ROWS * QKV_CH];
__device__ __align__(16) __half g_ath [N_ROWS * OUT_CH];

// ------------------------------ PTX helpers --------------------------------
__device__ __forceinline__ uint32_t smem_u32(const void* p) {
    uint32_t a;
    asm("{ .reg .u64 t; cvta.to.shared.u64 t, %1; cvt.u32.u64 %0, t; }"
        : "=r"(a) : "l"(p));
    return a;
}
#define CP_COMMIT() asm volatile("cp.async.commit_group;" ::: "memory")
#define CP_WAIT1()  asm volatile("cp.async.wait_group 1;" ::: "memory")
#define CP_WAIT2()  asm volatile("cp.async.wait_group 2;" ::: "memory")

__device__ __forceinline__ void cp16(uint32_t dst, const void* src) {
    asm volatile("cp.async.cg.shared.global [%0], [%1], 16;" :: "r"(dst), "l"(src));
}

__device__ __forceinline__ void ldsm_x4(uint32_t& r0, uint32_t& r1,
                                        uint32_t& r2, uint32_t& r3, uint32_t a) {
    asm volatile("ldmatrix.sync.aligned.m8n8.x4.shared.b16 {%0,%1,%2,%3}, [%4];"
                 : "=r"(r0), "=r"(r1), "=r"(r2), "=r"(r3) : "r"(a));
}

__device__ __forceinline__ void mma16816(float* d, const uint32_t* a, const uint32_t* b) {
    asm volatile(
        "mma.sync.aligned.m16n8k16.row.col.f32.f16.f16.f32 "
        "{%0,%1,%2,%3}, {%4,%5,%6,%7}, {%8,%9}, {%0,%1,%2,%3};"
        : "+f"(d[0]), "+f"(d[1]), "+f"(d[2]), "+f"(d[3])
        : "r"(a[0]), "r"(a[1]), "r"(a[2]), "r"(a[3]), "r"(b[0]), "r"(b[1]));
}

// ------------------------------ GEMM kernel --------------------------------
// 128 threads, 4 warps 2x2, warp tile 64x64, BK=32, 4-stage cp.async,
// fragment double-buffering across half-k steps.
// MODE 0: Cf = acc + bias                 (fp32 out)
// MODE 1: Ch = half(acc + bias + temb[m>>3])
// MODE 2: Ch = half(acc + bias)
template<int MODE>
__global__ __launch_bounds__(128, 2)
void gemm_mma(const __half* __restrict__ Ah, const __half* __restrict__ Bh,
              const float* __restrict__ bias, const float* __restrict__ temb,
              float* __restrict__ Cf, __half* __restrict__ Ch,
              int M, int N, int K)
{
    extern __shared__ __align__(128) char smem[];
    const uint32_t sb = smem_u32(smem);

    const int tid  = threadIdx.x;
    const int wid  = tid >> 5;
    const int lane = tid & 31;
    const int warp_m = wid & 1;
    const int warp_n = wid >> 1;
    const int m0 = blockIdx.y * BM;
    const int n0 = blockIdx.x * BN;

    // --- copy addressing (hoisted) ---
    const int cpc = tid & 3;                 // 16B chunk 0..3
    const int cpr = tid >> 2;                // base row 0..31
    const __half* gA = Ah + (size_t)(m0 + cpr) * K + cpc * 8;
    const __half* gB = Bh + (size_t)(n0 + cpr) * K + cpc * 8;
    const size_t rowstep = (size_t)32 * K;   // 32 rows
    uint32_t sOffA[4], sOffB[4];
#pragma unroll
    for (int j = 0; j < 4; j++) {
        const int r = cpr + j * 32;
        const uint32_t o = r * 64 + ((cpc ^ ((r >> 1) & 3)) << 4);
        sOffA[j] = o;
        sOffB[j] = A_BYTES + o;
    }

    float acc[4][8][4];
#pragma unroll
    for (int a = 0; a < 4; a++)
#pragma unroll
        for (int b = 0; b < 8; b++)
#pragma unroll
            for (int c = 0; c < 4; c++) acc[a][b][c] = 0.0f;

    const int KT = K / BK;

    // --- ldmatrix addressing (hoisted) ---
    const int lr = lane & 15;
    const int lc = lane >> 4;
    uint32_t aOff[2][4], bOff[2][4];
#pragma unroll
    for (int ks = 0; ks < 2; ks++) {
        const int ch = ks * 2 + lc;
#pragma unroll
        for (int f = 0; f < 4; f++) {
            const int ra = warp_m * 64 + f * 16 + lr;
            const int rb = warp_n * 64 + f * 16 + lr;
            aOff[ks][f] = ra * 64 + ((ch ^ ((ra >> 1) & 3)) << 4);
            bOff[ks][f] = A_BYTES + rb * 64 + ((ch ^ ((rb >> 1) & 3)) << 4);
        }
    }

    // --- prologue: 3 stages in flight ---
#pragma unroll
    for (int s = 0; s < 3; s++) {
        const uint32_t st = sb + s * STAGE_BYTES;
        const size_t k0 = (size_t)s * BK;
#pragma unroll
        for (int j = 0; j < 4; j++) {
            cp16(st + sOffA[j], gA + j * rowstep + k0);
            cp16(st + sOffB[j], gB + j * rowstep + k0);
        }
        CP_COMMIT();
    }
    CP_WAIT2();
    __syncthreads();

    uint32_t aF[2][4][4], bF[2][8][2];

    // preload fragments (kt=0, ks=0) into buffer 0
#pragma unroll
    for (int p = 0; p < 4; p++) {
        uint32_t r0, r1, r2, r3;
        ldsm_x4(r0, r1, r2, r3, sb + bOff[0][p]);
        bF[0][2 * p][0] = r0; bF[0][2 * p][1] = r2;
        bF[0][2 * p + 1][0] = r1; bF[0][2 * p + 1][1] = r3;
    }
#pragma unroll
    for (int mf = 0; mf < 4; mf++)
        ldsm_x4(aF[0][mf][0], aF[0][mf][1], aF[0][mf][2], aF[0][mf][3],
                sb + aOff[0][mf]);

#pragma unroll 1
    for (int kt = 0; kt < KT; kt++) {
        const uint32_t st = sb + (kt & 3) * STAGE_BYTES;

        // issue copy for stage kt+3 (slot safe: last readers synced at kt-1)
        if (kt + 3 < KT) {
            const uint32_t sn = sb + ((kt + 3) & 3) * STAGE_BYTES;
            const size_t k0 = (size_t)(kt + 3) * BK;
#pragma unroll
            for (int j = 0; j < 4; j++) {
                cp16(sn + sOffA[j], gA + j * rowstep + k0);
                cp16(sn + sOffB[j], gB + j * rowstep + k0);
            }
        }
        CP_COMMIT();

        // load buffer 1 with (kt, ks=1) fragments
#pragma unroll
        for (int p = 0; p < 4; p++) {
            uint32_t r0, r1, r2, r3;
            ldsm_x4(r0, r1, r2, r3, st + bOff[1][p]);
            bF[1][2 * p][0] = r0; bF[1][2 * p][1] = r2;
            bF[1][2 * p + 1][0] = r1; bF[1][2 * p + 1][1] = r3;
        }
#pragma unroll
        for (int mf = 0; mf < 4; mf++)
            ldsm_x4(aF[1][mf][0], aF[1][mf][1], aF[1][mf][2], aF[1][mf][3],
                    st + aOff[1][mf]);

        // MMA on buffer 0 (kt, ks=0)
#pragma unroll
        for (int mf = 0; mf < 4; mf++)
#pragma unroll
            for (int nf = 0; nf < 8; nf++)
                mma16816(acc[mf][nf], aF[0][mf], bF[0][nf]);

        if (kt < KT - 1) {
            CP_WAIT1();              // stage kt+1 (and kt+2) complete
            __syncthreads();         // visible to all; readers of old slot done
            const uint32_t stn = sb + ((kt + 1) & 3) * STAGE_BYTES;
#pragma unroll
            for (int p = 0; p < 4; p++) {
                uint32_t r0, r1, r2, r3;
                ldsm_x4(r0, r1, r2, r3, stn + bOff[0][p]);
                bF[0][2 * p][0] = r0; bF[0][2 * p][1] = r2;
                bF[0][2 * p + 1][0] = r1; bF[0][2 * p + 1][1] = r3;
            }
#pragma unroll
            for (int mf = 0; mf < 4; mf++)
                ldsm_x4(aF[0][mf][0], aF[0][mf][1], aF[0][mf][2], aF[0][mf][3],
                        stn + aOff[0][mf]);
        }

        // MMA on buffer 1 (kt, ks=1)
#pragma unroll
        for (int mf = 0; mf < 4; mf++)
#pragma unroll
            for (int nf = 0; nf < 8; nf++)
                mma16816(acc[mf][nf], aF[1][mf], bF[1][nf]);
    }

    // ------------------------------- epilogue ------------------------------
#pragma unroll
    for (int mf = 0; mf < 4; mf++)
#pragma unroll
        for (int nf = 0; nf < 8; nf++) {
            const int m = m0 + warp_m * 64 + mf * 16 + (lane >> 2);
            const int n = n0 + warp_n * 64 + nf * 8 + 2 * (lane & 3);
            const float* a = acc[mf][nf];
            const float b0 = bias[n], b1 = bias[n + 1];
            if (MODE == 0) {
                float2 v0 = make_float2(a[0] + b0, a[1] + b1);
                float2 v1 = make_float2(a[2] + b0, a[3] + b1);
                *reinterpret_cast<float2*>(Cf + (size_t)m * N + n) = v0;
                *reinterpret_cast<float2*>(Cf + (size_t)(m + 8) * N + n) = v1;
            } else if (MODE == 1) {
#pragma unroll
                for (int rr = 0; rr < 2; rr++) {
                    const int mm = m + rr * 8;
                    const float* tp = temb + (size_t)(mm >> 3) * OUT_CH + n;
                    const float v0 = a[rr * 2 + 0] + b0 + tp[0];
                    const float v1 = a[rr * 2 + 1] + b1 + tp[1];
                    *reinterpret_cast<__half2*>(Ch + (size_t)mm * N + n) =
                        __floats2half2_rn(v0, v1);
                }
            } else {
                *reinterpret_cast<__half2*>(Ch + (size_t)m * N + n) =
                    __floats2half2_rn(a[0] + b0, a[1] + b1);
                *reinterpret_cast<__half2*>(Ch + (size_t)(m + 8) * N + n) =
                    __floats2half2_rn(a[2] + b0, a[3] + b1);
            }
        }
}

// --------------------------- conversions (one launch) ----------------------
__device__ __forceinline__ void cvt4s(const float* __restrict__ s,
                                      __half* __restrict__ h, int i)
{
    float4 v = *reinterpret_cast<const float4*>(s + i);
    __half2 a = __floats2half2_rn(v.x, v.y);
    __half2 b = __floats2half2_rn(v.z, v.w);
    *reinterpret_cast<uint2*>(h + i) =
        make_uint2(*reinterpret_cast<uint32_t*>(&a), *reinterpret_cast<uint32_t*>(&b));
}

static constexpr int SZ_X  = N_ROWS * IN_CH;
static constexpr int SZ_T  = N_BATCH * T_DIM;
static constexpr int SZ_WD = OUT_CH * IN_CH;
static constexpr int SZ_WT = OUT_CH * T_DIM;
static constexpr int SZ_WQ = QKV_CH * OUT_CH;
static constexpr int SZ_WO = OUT_CH * OUT_CH;
static constexpr int C0 = SZ_X,       C1 = C0 + SZ_T,  C2 = C1 + SZ_WD;
static constexpr int C3 = C2 + SZ_WT, C4 = C3 + SZ_WQ, C5 = C4 + SZ_WO;
static constexpr int CVT_BLOCKS = C5 / 4 / 256;

__global__ __launch_bounds__(256)
void cvt_all(const float* __restrict__ x,  const float* __restrict__ t,
             const float* __restrict__ Wd, const float* __restrict__ Wt,
             const float* __restrict__ Wq, const float* __restrict__ Wo,
             __half* __restrict__ xh,  __half* __restrict__ th,
             __half* __restrict__ Wdh, __half* __restrict__ Wth,
             __half* __restrict__ Wqh, __half* __restrict__ Woh)
{
    int i = (blockIdx.x * 256 + threadIdx.x) * 4;
    if (i < C0)      cvt4s(x,  xh,  i);
    else if (i < C1) cvt4s(t,  th,  i - C0);
    else if (i < C2) cvt4s(Wd, Wdh, i - C1);
    else if (i < C3) cvt4s(Wt, Wth, i - C2);
    else if (i < C4) cvt4s(Wq, Wqh, i - C3);
    else             cvt4s(Wo, Woh, i - C4);
}

// ------------------------------ attention ----------------------------------
// fp16 qkv in, fp16 att out. Padded smem: each 64-half group padded to 72
// halves (9 uint4) -> row stride 1728 halves (216 uint4).
__device__ __forceinline__ void unpack8(float* f, uint4 u) {
    const __half2* h = reinterpret_cast<const __half2*>(&u);
#pragma unroll
    for (int k = 0; k < 4; k++) {
        float2 v = __half22float2(h[k]);
        f[2 * k] = v.x; f[2 * k + 1] = v.y;
    }
}

__global__ __launch_bounds__(256)
void attn_kernel(const __half* __restrict__ qkv, __half* __restrict__ oh)
{
    __shared__ __half s[8 * 1728];   // 27648 B
    const int tid = threadIdx.x;
    const size_t row0 = (size_t)blockIdx.x * 8;

    const uint4* src = reinterpret_cast<const uint4*>(qkv + row0 * QKV_CH);
    uint4* dst = reinterpret_cast<uint4*>(s);
#pragma unroll
    for (int it = 0; it < 6; it++) {
        int idx = tid + it * 256;                // 0..1535
        int r = idx / 192, j = idx - r * 192;    // row, uint4-in-row
        int grp = j >> 3, w8 = j & 7;
        dst[r * 216 + grp * 9 + w8] = src[idx];
    }
    __syncthreads();

    const int warp = tid >> 5;
    const int lane = tid & 31;
    const __half* qs = s + warp * 1728;
    const int i  = lane & 7;
    const int c0 = (lane >> 3) * 16;

    float qreg[16];
    {
        const __half* qp = qs + i * 72 + c0;
        unpack8(qreg,     *reinterpret_cast<const uint4*>(qp));
        unpack8(qreg + 8, *reinterpret_cast<const uint4*>(qp + 8));
    }

    float w[8];
#pragma unroll
    for (int j = 0; j < 8; j++) {
        const __half* kp = qs + (8 + j) * 72 + c0;
        float kr[16];
        unpack8(kr,     *reinterpret_cast<const uint4*>(kp));
        unpack8(kr + 8, *reinterpret_cast<const uint4*>(kp + 8));
        float acc = 0.0f;
#pragma unroll
        for (int c = 0; c < 16; c++) acc = fmaf(qreg[c], kr[c], acc);
        acc += __shfl_xor_sync(0xffffffffu, acc, 8);
        acc += __shfl_xor_sync(0xffffffffu, acc, 16);
        w[j] = acc * 0.125f;
    }

    float mx = w[0];
#pragma unroll
    for (int j = 1; j < 8; j++) mx = fmaxf(mx, w[j]);
    float sum = 0.0f;
#pragma unroll
    for (int j = 0; j < 8; j++) { w[j] = __expf(w[j] - mx); sum += w[j]; }
    const float inv = 1.0f / sum;

    float o[16];
#pragma unroll
    for (int c = 0; c < 16; c++) o[c] = 0.0f;
#pragma unroll
    for (int j = 0; j < 8; j++) {
        const __half* vp = qs + (16 + j) * 72 + c0;
        float vr[16];
        unpack8(vr,     *reinterpret_cast<const uint4*>(vp));
        unpack8(vr + 8, *reinterpret_cast<const uint4*>(vp + 8));
        const float wj = w[j];
#pragma unroll
        for (int c = 0; c < 16; c++) o[c] = fmaf(wj, vr[c], o[c]);
    }

    __half* op = oh + (row0 + warp) * (size_t)OUT_CH + i * 64 + c0;
    uint32_t pk[8];
#pragma unroll
    for (int p = 0; p < 8; p++) {
        __half2 h = __floats2half2_rn(o[2 * p] * inv, o[2 * p + 1] * inv);
        pk[p] = *reinterpret_cast<uint32_t*>(&h);
    }
    *reinterpret_cast<uint4*>(op)     = make_uint4(pk[0], pk[1], pk[2], pk[3]);
    *reinterpret_cast<uint4*>(op + 8) = make_uint4(pk[4], pk[5], pk[6], pk[7]);
}

// ---------------------------------------------------------------------------
extern "C" void kernel_launch(void* const* d_in, const int* in_sizes, int n_in,
                              void* d_out, int out_size)
{
    const float* x      = (const float*)d_in[0];
    const float* t      = (const float*)d_in[1];
    const float* W_down = (const float*)d_in[2];
    const float* b_down = (const float*)d_in[3];
    const float* W_t    = (const float*)d_in[4];
    const float* b_t    = (const float*)d_in[5];
    const float* W_qkv  = (const float*)d_in[6];
    const float* b_qkv  = (const float*)d_in[7];
    const float* W_out  = (const float*)d_in[8];
    const float* b_out  = (const float*)d_in[9];
    float* out = (float*)d_out;

    __half *xh, *th, *Wdh, *Wth, *Wqh, *Woh, *yh, *qkvh, *ath;
    float *temb;
    cudaGetSymbolAddress((void**)&xh,   g_xh);
    cudaGetSymbolAddress((void**)&th,   g_th);
    cudaGetSymbolAddress((void**)&Wdh,  g_Wdh);
    cudaGetSymbolAddress((void**)&Wth,  g_Wth);
    cudaGetSymbolAddress((void**)&Wqh,  g_Wqh);
    cudaGetSymbolAddress((void**)&Woh,  g_Woh);
    cudaGetSymbolAddress((void**)&temb, g_temb);
    cudaGetSymbolAddress((void**)&yh,   g_yh);
    cudaGetSymbolAddress((void**)&qkvh, g_qkvh);
    cudaGetSymbolAddress((void**)&ath,  g_ath);

    cudaFuncSetAttribute(gemm_mma<0>, cudaFuncAttributeMaxDynamicSharedMemorySize, SMEM_BYTES);
    cudaFuncSetAttribute(gemm_mma<1>, cudaFuncAttributeMaxDynamicSharedMemorySize, SMEM_BYTES);
    cudaFuncSetAttribute(gemm_mma<2>, cudaFuncAttributeMaxDynamicSharedMemorySize, SMEM_BYTES);

    // launch 0: conversions
    cvt_all<<<CVT_BLOCKS, 256>>>(x, t, W_down, W_t, W_qkv, W_out,
                                 xh, th, Wdh, Wth, Wqh, Woh);

    // launch 1: temb = t @ W_t^T + b_t             [8192, 512] fp32
    gemm_mma<0><<<dim3(OUT_CH / BN, N_BATCH / BM), 128, SMEM_BYTES>>>(
        th, Wth, b_t, nullptr, temb, nullptr, N_BATCH, OUT_CH, T_DIM);

    // launch 2: y = x @ W_down^T + b_down + temb   -> fp16
    gemm_mma<1><<<dim3(OUT_CH / BN, N_ROWS / BM), 128, SMEM_BYTES>>>(
        xh, Wdh, b_down, temb, nullptr, yh, N_ROWS, OUT_CH, IN_CH);

    // launch 3: qkv = y @ W_qkv^T + b_qkv          -> fp16
    gemm_mma<2><<<dim3(QKV_CH / BN, N_ROWS / BM), 128, SMEM_BYTES>>>(
        yh, Wqh, b_qkv, nullptr, nullptr, qkvh, N_ROWS, QKV_CH, OUT_CH);

    // launch 4: att = rowwise attention(qkv)       -> fp16
    attn_kernel<<<N_ROWS / 8, 256>>>(qkvh, ath);

    // launch 5 (ncu capture target): out = att @ W_out^T + b_out (fp32)
    gemm_mma<0><<<dim3(OUT_CH / BN, N_ROWS / BM), 128, SMEM_BYTES>>>(
        ath, Woh, b_out, nullptr, out, nullptr, N_ROWS, OUT_CH, OUT_CH);
}

// round 9
// speedup vs baseline: 7.2461x; 1.0704x over previous
#include <cuda_runtime.h>
#include <cuda_fp16.h>
#include <cstdint>

// ---------------------------------------------------------------------------
// TSABlock — fp16 mma.sync GEMMs, BK=64, 3-stage cp.async (Round 8)
// ---------------------------------------------------------------------------

#define N_ROWS   65536
#define N_BATCH  8192
#define IN_CH    1024
#define OUT_CH   512
#define T_DIM    512
#define QKV_CH   1536

#define BM 128
#define BN 128
#define BK 64
static constexpr int A_BYTES = BM * 128;                // 16 KB (128 rows x 128 B)
static constexpr int B_BYTES = BN * 128;                // 16 KB
static constexpr int STAGE_BYTES = A_BYTES + B_BYTES;   // 32 KB
static constexpr int NSTAGE = 3;
static constexpr int SMEM_BYTES = NSTAGE * STAGE_BYTES; // 96 KB

// ------------------------- device scratch (no cudaMalloc) -------------------
__device__ __align__(16) __half g_xh  [N_ROWS * IN_CH];
__device__ __align__(16) __half g_th  [N_BATCH * T_DIM];
__device__ __align__(16) __half g_Wdh [OUT_CH * IN_CH];
__device__ __align__(16) __half g_Wth [OUT_CH * T_DIM];
__device__ __align__(16) __half g_Wqh [QKV_CH * OUT_CH];
__device__ __align__(16) __half g_Woh [OUT_CH * OUT_CH];
__device__ __align__(16) float  g_temb[N_BATCH * OUT_CH];
__device__ __align__(16) __half g_yh  [N_ROWS * OUT_CH];
__device__ __align__(16) __half g_qkvh[N_ROWS * QKV_CH];
__device__ __align__(16) __half g_ath [N_ROWS * OUT_CH];

// ------------------------------ PTX helpers --------------------------------
__device__ __forceinline__ uint32_t smem_u32(const void* p) {
    uint32_t a;
    asm("{ .reg .u64 t; cvta.to.shared.u64 t, %1; cvt.u32.u64 %0, t; }"
        : "=r"(a) : "l"(p));
    return a;
}
#define CP_COMMIT() asm volatile("cp.async.commit_group;" ::: "memory")
#define CP_WAIT1()  asm volatile("cp.async.wait_group 1;" ::: "memory")

__device__ __forceinline__ void cp16(uint32_t dst, const void* src) {
    asm volatile("cp.async.cg.shared.global [%0], [%1], 16;" :: "r"(dst), "l"(src));
}

__device__ __forceinline__ void ldsm_x4(uint32_t& r0, uint32_t& r1,
                                        uint32_t& r2, uint32_t& r3, uint32_t a) {
    asm volatile("ldmatrix.sync.aligned.m8n8.x4.shared.b16 {%0,%1,%2,%3}, [%4];"
                 : "=r"(r0), "=r"(r1), "=r"(r2), "=r"(r3) : "r"(a));
}

__device__ __forceinline__ void mma16816(float* d, const uint32_t* a, const uint32_t* b) {
    asm volatile(
        "mma.sync.aligned.m16n8k16.row.col.f32.f16.f16.f32 "
        "{%0,%1,%2,%3}, {%4,%5,%6,%7}, {%8,%9}, {%0,%1,%2,%3};"
        : "+f"(d[0]), "+f"(d[1]), "+f"(d[2]), "+f"(d[3])
        : "r"(a[0]), "r"(a[1]), "r"(a[2]), "r"(a[3]), "r"(b[0]), "r"(b[1]));
}

// ------------------------------ GEMM kernel --------------------------------
// 128 threads, 4 warps 2x2, warp tile 64x64, BK=64, 3-stage cp.async,
// fragment double-buffering across the 4 half-k steps.
// MODE 0: Cf = acc + bias
// MODE 1: Ch = half(acc + bias + temb[m>>3])
// MODE 2: Ch = half(acc + bias)
template<int MODE>
__global__ __launch_bounds__(128, 2)
void gemm_mma(const __half* __restrict__ Ah, const __half* __restrict__ Bh,
              const float* __restrict__ bias, const float* __restrict__ temb,
              float* __restrict__ Cf, __half* __restrict__ Ch,
              int M, int N, int K)
{
    extern __shared__ __align__(128) char smem[];
    const uint32_t sb = smem_u32(smem);

    const int tid  = threadIdx.x;
    const int wid  = tid >> 5;
    const int lane = tid & 31;
    const int warp_m = wid & 1;
    const int warp_n = wid >> 1;
    const int m0 = blockIdx.y * BM;
    const int n0 = blockIdx.x * BN;

    // --- copy addressing: cpc = 16B chunk 0..7, cpr = base row 0..15 ---
    const int cpc = tid & 7;
    const int cpr = tid >> 3;
    const __half* gA = Ah + (size_t)(m0 + cpr) * K + cpc * 8;
    const __half* gB = Bh + (size_t)(n0 + cpr) * K + cpc * 8;
    const size_t rowstep = (size_t)16 * K;      // 16 rows per j
    const uint32_t swz = cpr * 128 + (((cpc ^ (cpr & 7))) << 4);  // row&7 const over j

    float acc[4][8][4];
#pragma unroll
    for (int a = 0; a < 4; a++)
#pragma unroll
        for (int b = 0; b < 8; b++)
#pragma unroll
            for (int c = 0; c < 4; c++) acc[a][b][c] = 0.0f;

    const int KT = K / BK;

    // --- ldmatrix base offsets (XOR-folded):  addr = base[f] ^ (ks<<5) ---
    const int lr = lane & 15;
    const int lc = lane >> 4;
    uint32_t aBase[4], bBase[4];
#pragma unroll
    for (int f = 0; f < 4; f++) {
        const int ra = warp_m * 64 + f * 16 + lr;
        const int rb = warp_n * 64 + f * 16 + lr;
        aBase[f] = ra * 128 + ((((ra & 7) ^ lc)) << 4);
        bBase[f] = A_BYTES + rb * 128 + ((((rb & 7) ^ lc)) << 4);
    }

    // --- prologue: stages 0,1 ---
#pragma unroll
    for (int s = 0; s < 2; s++) {
        const uint32_t st = sb + s * STAGE_BYTES;
        const size_t k0 = (size_t)s * BK;
#pragma unroll
        for (int j = 0; j < 8; j++) {
            cp16(st + swz + j * 2048, gA + j * rowstep + k0);
            cp16(st + A_BYTES + swz + j * 2048, gB + j * rowstep + k0);
        }
        CP_COMMIT();
    }
    CP_WAIT1();
    __syncthreads();

    uint32_t aF[2][4][4], bF[2][8][2];

    // preload (kt=0, ks=0) into buf0
#pragma unroll
    for (int p = 0; p < 4; p++) {
        uint32_t r0, r1, r2, r3;
        ldsm_x4(r0, r1, r2, r3, sb + bBase[p]);
        bF[0][2 * p][0] = r0; bF[0][2 * p][1] = r2;
        bF[0][2 * p + 1][0] = r1; bF[0][2 * p + 1][1] = r3;
    }
#pragma unroll
    for (int mf = 0; mf < 4; mf++)
        ldsm_x4(aF[0][mf][0], aF[0][mf][1], aF[0][mf][2], aF[0][mf][3],
                sb + aBase[mf]);

#pragma unroll 1
    for (int kt = 0; kt < KT; kt++) {
        const uint32_t st = sb + (kt % NSTAGE) * STAGE_BYTES;

        // copy stage kt+2 into slot (kt+2)%3 (its last readers synced at kt-1)
        if (kt + 2 < KT) {
            const uint32_t sn = sb + ((kt + 2) % NSTAGE) * STAGE_BYTES;
            const size_t k0 = (size_t)(kt + 2) * BK;
#pragma unroll
            for (int j = 0; j < 8; j++) {
                cp16(sn + swz + j * 2048, gA + j * rowstep + k0);
                cp16(sn + A_BYTES + swz + j * 2048, gB + j * rowstep + k0);
            }
        }
        CP_COMMIT();

#pragma unroll
        for (int ks = 0; ks < 4; ks++) {
            const int cur = ks & 1;
            const int nxt = cur ^ 1;
            if (ks < 3) {
                // load (kt, ks+1) into other buffer
                const uint32_t x = (uint32_t)(ks + 1) << 5;
#pragma unroll
                for (int p = 0; p < 4; p++) {
                    uint32_t r0, r1, r2, r3;
                    ldsm_x4(r0, r1, r2, r3, st + (bBase[p] ^ x));
                    bF[nxt][2 * p][0] = r0; bF[nxt][2 * p][1] = r2;
                    bF[nxt][2 * p + 1][0] = r1; bF[nxt][2 * p + 1][1] = r3;
                }
#pragma unroll
                for (int mf = 0; mf < 4; mf++)
                    ldsm_x4(aF[nxt][mf][0], aF[nxt][mf][1],
                            aF[nxt][mf][2], aF[nxt][mf][3], st + (aBase[mf] ^ x));
            } else if (kt < KT - 1) {
                // next stage ready?  groups pending ≤1 → stage kt+1 complete
                CP_WAIT1();
                __syncthreads();
                const uint32_t stn = sb + ((kt + 1) % NSTAGE) * STAGE_BYTES;
#pragma unroll
                for (int p = 0; p < 4; p++) {
                    uint32_t r0, r1, r2, r3;
                    ldsm_x4(r0, r1, r2, r3, stn + bBase[p]);
                    bF[nxt][2 * p][0] = r0; bF[nxt][2 * p][1] = r2;
                    bF[nxt][2 * p + 1][0] = r1; bF[nxt][2 * p + 1][1] = r3;
                }
#pragma unroll
                for (int mf = 0; mf < 4; mf++)
                    ldsm_x4(aF[nxt][mf][0], aF[nxt][mf][1],
                            aF[nxt][mf][2], aF[nxt][mf][3], stn + aBase[mf]);
            }
#pragma unroll
            for (int mf = 0; mf < 4; mf++)
#pragma unroll
                for (int nf = 0; nf < 8; nf++)
                    mma16816(acc[mf][nf], aF[cur][mf], bF[cur][nf]);
        }
    }

    // ------------------------------- epilogue ------------------------------
#pragma unroll
    for (int mf = 0; mf < 4; mf++)
#pragma unroll
        for (int nf = 0; nf < 8; nf++) {
            const int m = m0 + warp_m * 64 + mf * 16 + (lane >> 2);
            const int n = n0 + warp_n * 64 + nf * 8 + 2 * (lane & 3);
            const float* a = acc[mf][nf];
            const float b0 = bias[n], b1 = bias[n + 1];
            if (MODE == 0) {
                float2 v0 = make_float2(a[0] + b0, a[1] + b1);
                float2 v1 = make_float2(a[2] + b0, a[3] + b1);
                *reinterpret_cast<float2*>(Cf + (size_t)m * N + n) = v0;
                *reinterpret_cast<float2*>(Cf + (size_t)(m + 8) * N + n) = v1;
            } else if (MODE == 1) {
#pragma unroll
                for (int rr = 0; rr < 2; rr++) {
                    const int mm = m + rr * 8;
                    const float* tp = temb + (size_t)(mm >> 3) * OUT_CH + n;
                    const float v0 = a[rr * 2 + 0] + b0 + tp[0];
                    const float v1 = a[rr * 2 + 1] + b1 + tp[1];
                    *reinterpret_cast<__half2*>(Ch + (size_t)mm * N + n) =
                        __floats2half2_rn(v0, v1);
                }
            } else {
                *reinterpret_cast<__half2*>(Ch + (size_t)m * N + n) =
                    __floats2half2_rn(a[0] + b0, a[1] + b1);
                *reinterpret_cast<__half2*>(Ch + (size_t)(m + 8) * N + n) =
                    __floats2half2_rn(a[2] + b0, a[3] + b1);
            }
        }
}

// --------------------------- conversions (one launch) ----------------------
__device__ __forceinline__ void cvt4s(const float* __restrict__ s,
                                      __half* __restrict__ h, int i)
{
    float4 v = *reinterpret_cast<const float4*>(s + i);
    __half2 a = __floats2half2_rn(v.x, v.y);
    __half2 b = __floats2half2_rn(v.z, v.w);
    *reinterpret_cast<uint2*>(h + i) =
        make_uint2(*reinterpret_cast<uint32_t*>(&a), *reinterpret_cast<uint32_t*>(&b));
}

static constexpr int SZ_X  = N_ROWS * IN_CH;
static constexpr int SZ_T  = N_BATCH * T_DIM;
static constexpr int SZ_WD = OUT_CH * IN_CH;
static constexpr int SZ_WT = OUT_CH * T_DIM;
static constexpr int SZ_WQ = QKV_CH * OUT_CH;
static constexpr int SZ_WO = OUT_CH * OUT_CH;
static constexpr int C0 = SZ_X,       C1 = C0 + SZ_T,  C2 = C1 + SZ_WD;
static constexpr int C3 = C2 + SZ_WT, C4 = C3 + SZ_WQ, C5 = C4 + SZ_WO;
static constexpr int CVT_BLOCKS = C5 / 4 / 256;

__global__ __launch_bounds__(256)
void cvt_all(const float* __restrict__ x,  const float* __restrict__ t,
             const float* __restrict__ Wd, const float* __restrict__ Wt,
             const float* __restrict__ Wq, const float* __restrict__ Wo,
             __half* __restrict__ xh,  __half* __restrict__ th,
             __half* __restrict__ Wdh, __half* __restrict__ Wth,
             __half* __restrict__ Wqh, __half* __restrict__ Woh)
{
    int i = (blockIdx.x * 256 + threadIdx.x) * 4;
    if (i < C0)      cvt4s(x,  xh,  i);
    else if (i < C1) cvt4s(t,  th,  i - C0);
    else if (i < C2) cvt4s(Wd, Wdh, i - C1);
    else if (i < C3) cvt4s(Wt, Wth, i - C2);
    else if (i < C4) cvt4s(Wq, Wqh, i - C3);
    else             cvt4s(Wo, Woh, i - C4);
}

// ------------------------------ attention ----------------------------------
__device__ __forceinline__ void unpack8(float* f, uint4 u) {
    const __half2* h = reinterpret_cast<const __half2*>(&u);
#pragma unroll
    for (int k = 0; k < 4; k++) {
        float2 v = __half22float2(h[k]);
        f[2 * k] = v.x; f[2 * k + 1] = v.y;
    }
}

__global__ __launch_bounds__(256)
void attn_kernel(const __half* __restrict__ qkv, __half* __restrict__ oh)
{
    __shared__ __half s[8 * 1728];   // 27648 B (64-half groups padded to 72)
    const int tid = threadIdx.x;
    const size_t row0 = (size_t)blockIdx.x * 8;

    const uint4* src = reinterpret_cast<const uint4*>(qkv + row0 * QKV_CH);
    uint4* dst = reinterpret_cast<uint4*>(s);
#pragma unroll
    for (int it = 0; it < 6; it++) {
        int idx = tid + it * 256;                // 0..1535
        int r = idx / 192, j = idx - r * 192;
        int grp = j >> 3, w8 = j & 7;
        dst[r * 216 + grp * 9 + w8] = src[idx];
    }
    __syncthreads();

    const int warp = tid >> 5;
    const int lane = tid & 31;
    const __half* qs = s + warp * 1728;
    const int i  = lane & 7;
    const int c0 = (lane >> 3) * 16;

    float qreg[16];
    {
        const __half* qp = qs + i * 72 + c0;
        unpack8(qreg,     *reinterpret_cast<const uint4*>(qp));
        unpack8(qreg + 8, *reinterpret_cast<const uint4*>(qp + 8));
    }

    float w[8];
#pragma unroll
    for (int j = 0; j < 8; j++) {
        const __half* kp = qs + (8 + j) * 72 + c0;
        float kr[16];
        unpack8(kr,     *reinterpret_cast<const uint4*>(kp));
        unpack8(kr + 8, *reinterpret_cast<const uint4*>(kp + 8));
        float acc = 0.0f;
#pragma unroll
        for (int c = 0; c < 16; c++) acc = fmaf(qreg[c], kr[c], acc);
        acc += __shfl_xor_sync(0xffffffffu, acc, 8);
        acc += __shfl_xor_sync(0xffffffffu, acc, 16);
        w[j] = acc * 0.125f;
    }

    float mx = w[0];
#pragma unroll
    for (int j = 1; j < 8; j++) mx = fmaxf(mx, w[j]);
    float sum = 0.0f;
#pragma unroll
    for (int j = 0; j < 8; j++) { w[j] = __expf(w[j] - mx); sum += w[j]; }
    const float inv = 1.0f / sum;

    float o[16];
#pragma unroll
    for (int c = 0; c < 16; c++) o[c] = 0.0f;
#pragma unroll
    for (int j = 0; j < 8; j++) {
        const __half* vp = qs + (16 + j) * 72 + c0;
        float vr[16];
        unpack8(vr,     *reinterpret_cast<const uint4*>(vp));
        unpack8(vr + 8, *reinterpret_cast<const uint4*>(vp + 8));
        const float wj = w[j];
#pragma unroll
        for (int c = 0; c < 16; c++) o[c] = fmaf(wj, vr[c], o[c]);
    }

    __half* op = oh + (row0 + warp) * (size_t)OUT_CH + i * 64 + c0;
    uint32_t pk[8];
#pragma unroll
    for (int p = 0; p < 8; p++) {
        __half2 h = __floats2half2_rn(o[2 * p] * inv, o[2 * p + 1] * inv);
        pk[p] = *reinterpret_cast<uint32_t*>(&h);
    }
    *reinterpret_cast<uint4*>(op)     = make_uint4(pk[0], pk[1], pk[2], pk[3]);
    *reinterpret_cast<uint4*>(op + 8) = make_uint4(pk[4], pk[5], pk[6], pk[7]);
}

// ---------------------------------------------------------------------------
extern "C" void kernel_launch(void* const* d_in, const int* in_sizes, int n_in,
                              void* d_out, int out_size)
{
    const float* x      = (const float*)d_in[0];
    const float* t      = (const float*)d_in[1];
    const float* W_down = (const float*)d_in[2];
    const float* b_down = (const float*)d_in[3];
    const float* W_t    = (const float*)d_in[4];
    const float* b_t    = (const float*)d_in[5];
    const float* W_qkv  = (const float*)d_in[6];
    const float* b_qkv  = (const float*)d_in[7];
    const float* W_out  = (const float*)d_in[8];
    const float* b_out  = (const float*)d_in[9];
    float* out = (float*)d_out;

    __half *xh, *th, *Wdh, *Wth, *Wqh, *Woh, *yh, *qkvh, *ath;
    float *temb;
    cudaGetSymbolAddress((void**)&xh,   g_xh);
    cudaGetSymbolAddress((void**)&th,   g_th);
    cudaGetSymbolAddress((void**)&Wdh,  g_Wdh);
    cudaGetSymbolAddress((void**)&Wth,  g_Wth);
    cudaGetSymbolAddress((void**)&Wqh,  g_Wqh);
    cudaGetSymbolAddress((void**)&Woh,  g_Woh);
    cudaGetSymbolAddress((void**)&temb, g_temb);
    cudaGetSymbolAddress((void**)&yh,   g_yh);
    cudaGetSymbolAddress((void**)&qkvh, g_qkvh);
    cudaGetSymbolAddress((void**)&ath,  g_ath);

    cudaFuncSetAttribute(gemm_mma<0>, cudaFuncAttributeMaxDynamicSharedMemorySize, SMEM_BYTES);
    cudaFuncSetAttribute(gemm_mma<1>, cudaFuncAttributeMaxDynamicSharedMemorySize, SMEM_BYTES);
    cudaFuncSetAttribute(gemm_mma<2>, cudaFuncAttributeMaxDynamicSharedMemorySize, SMEM_BYTES);

    // launch 0: conversions
    cvt_all<<<CVT_BLOCKS, 256>>>(x, t, W_down, W_t, W_qkv, W_out,
                                 xh, th, Wdh, Wth, Wqh, Woh);

    // launch 1: temb = t @ W_t^T + b_t             [8192, 512] fp32
    gemm_mma<0><<<dim3(OUT_CH / BN, N_BATCH / BM), 128, SMEM_BYTES>>>(
        th, Wth, b_t, nullptr, temb, nullptr, N_BATCH, OUT_CH, T_DIM);

    // launch 2: y = x @ W_down^T + b_down + temb   -> fp16
    gemm_mma<1><<<dim3(OUT_CH / BN, N_ROWS / BM), 128, SMEM_BYTES>>>(
        xh, Wdh, b_down, temb, nullptr, yh, N_ROWS, OUT_CH, IN_CH);

    // launch 3: qkv = y @ W_qkv^T + b_qkv          -> fp16
    gemm_mma<2><<<dim3(QKV_CH / BN, N_ROWS / BM), 128, SMEM_BYTES>>>(
        yh, Wqh, b_qkv, nullptr, nullptr, qkvh, N_ROWS, QKV_CH, OUT_CH);

    // launch 4: att = rowwise attention(qkv)       -> fp16
    attn_kernel<<<N_ROWS / 8, 256>>>(qkvh, ath);

    // launch 5 (ncu capture target): out = att @ W_out^T + b_out (fp32)
    gemm_mma<0><<<dim3(OUT_CH / BN, N_ROWS / BM), 128, SMEM_BYTES>>>(
        ath, Woh, b_out, nullptr, out, nullptr, N_ROWS, OUT_CH, OUT_CH);
}